// round 2
// baseline (speedup 1.0000x reference)
#include <cuda_runtime.h>
#include <math.h>

#define N   4096
#define S0  256
#define S1  128
#define S2  64

// ---------------- scratch (device globals; no allocations allowed) ----------
__device__ __align__(16) float g_W2[N * S2];     // (U0@U1)@U2            [N,64]
__device__ __align__(16) float g_C [N * S2];     // A @ V2^T              [N,64]
__device__ __align__(16) float g_hn[N * S0];     // row-normalized h      [N,256]
__device__ float g_G1[S2 * S2];                  // W2^T W2
__device__ float g_G2[S2 * S2];                  // V2 V2^T
__device__ float g_total [N];
__device__ float g_possim[N];
__device__ float g_posclq[N];
__device__ float g_posngh[N];
// 0: sumsq(A)  1: <W2, A V2^T>  2: <G1,G2>  3: loss5
// 4: clique -log sum  5: neighbor -log sum  6: sim -log sum
__device__ double g_acc[8];

// ---------------- helpers ---------------------------------------------------
__device__ __forceinline__ float blockReduceSum(float v) {
    __shared__ float sh[33];
    int lane = threadIdx.x & 31, w = threadIdx.x >> 5;
#pragma unroll
    for (int o = 16; o; o >>= 1) v += __shfl_down_sync(0xffffffffu, v, o);
    if (lane == 0) sh[w] = v;
    __syncthreads();
    if (threadIdx.x == 0) {
        int nw = (blockDim.x + 31) >> 5;
        float r = 0.f;
        for (int x = 0; x < nw; x++) r += sh[x];
        sh[32] = r;
    }
    __syncthreads();
    float r = sh[32];
    __syncthreads();   // safe for repeated calls
    return r;
}

// ---------------- zero scratch (graph replays must be deterministic) --------
__global__ void k_zero() {
    int tid = blockIdx.x * blockDim.x + threadIdx.x;
    int stride = gridDim.x * blockDim.x;
    for (int i = tid; i < N * S2; i += stride) g_C[i] = 0.f;
    for (int i = tid; i < S2 * S2; i += stride) { g_G1[i] = 0.f; g_G2[i] = 0.f; }
    for (int i = tid; i < N; i += stride) {
        g_total[i] = 0.f; g_possim[i] = 0.f; g_posclq[i] = 0.f; g_posngh[i] = 0.f;
    }
    if (tid < 8) g_acc[tid] = 0.0;
}

// ---------------- W2 = (U0 @ U1) @ U2, one block per row -------------------
__global__ __launch_bounds__(128) void k_factor(const float* __restrict__ U0,
                                                const float* __restrict__ U1,
                                                const float* __restrict__ U2) {
    __shared__ float sU0[S0];
    __shared__ float sW1[S1];
    int i = blockIdx.x, t = threadIdx.x;
    sU0[t]       = U0[i * S0 + t];
    sU0[t + 128] = U0[i * S0 + t + 128];
    __syncthreads();
    float acc = 0.f;
#pragma unroll 8
    for (int k = 0; k < S0; k++) acc += sU0[k] * U1[k * S1 + t];
    sW1[t] = acc;
    __syncthreads();
    if (t < S2) {
        float a = 0.f;
#pragma unroll 8
        for (int k = 0; k < S1; k++) a += sW1[k] * U2[k * S2 + t];
        g_W2[i * S2 + t] = a;
    }
}

// ------------ hn = l2norm_rows( elu(V2^T fc1^T + b1) fc2^T + b2 ) ----------
__global__ __launch_bounds__(256) void k_proj(const float* __restrict__ V2,
                                              const float* __restrict__ fc1w,
                                              const float* __restrict__ fc1b,
                                              const float* __restrict__ fc2w,
                                              const float* __restrict__ fc2b) {
    __shared__ float sV[S2];
    __shared__ float sH1[S1];
    int n = blockIdx.x, t = threadIdx.x;
    if (t < S2) sV[t] = V2[t * N + n];
    __syncthreads();
    if (t < S1) {
        float a = fc1b[t];
#pragma unroll 8
        for (int s = 0; s < S2; s++) a += sV[s] * fc1w[t * S2 + s];
        sH1[t] = (a > 0.f) ? a : expm1f(a);   // elu, alpha=1
    }
    __syncthreads();
    float a = fc2b[t];
#pragma unroll 8
    for (int s = 0; s < S1; s++) a += sH1[s] * fc2w[t * S1 + s];
    float ss = blockReduceSum(a * a);
    float inv = 1.f / fmaxf(sqrtf(ss), 1e-12f);
    g_hn[n * S0 + t] = a * inv;
}

// ---------------- G1 = W2^T W2 (64x64) --------------------------------------
__global__ __launch_bounds__(256) void k_gram1() {
    __shared__ float tw[32 * 65];
    int t = threadIdx.x;
    float a[16];
#pragma unroll
    for (int q = 0; q < 16; q++) a[q] = 0.f;
    int base = blockIdx.x * 128;   // 32 blocks * 128 rows = 4096
    for (int c = 0; c < 4; c++) {
#pragma unroll
        for (int q = 0; q < 8; q++) {
            int e = t + q * 256;
            int r = e >> 6, k = e & 63;
            tw[r * 65 + k] = g_W2[(base + c * 32 + r) * S2 + k];
        }
        __syncthreads();
        for (int r = 0; r < 32; r++) {
#pragma unroll
            for (int q = 0; q < 16; q++) {
                int p = t * 16 + q;
                a[q] += tw[r * 65 + (p >> 6)] * tw[r * 65 + (p & 63)];
            }
        }
        __syncthreads();
    }
#pragma unroll
    for (int q = 0; q < 16; q++) atomicAdd(&g_G1[t * 16 + q], a[q]);
}

// ---------------- G2 = V2 V2^T (64x64) --------------------------------------
__global__ __launch_bounds__(256) void k_gram2(const float* __restrict__ V2) {
    __shared__ float tv[S2 * 33];
    int t = threadIdx.x;
    float a[16];
#pragma unroll
    for (int q = 0; q < 16; q++) a[q] = 0.f;
    int jbase = blockIdx.x * 128;  // 32 blocks * 128 cols = 4096
    for (int c = 0; c < 4; c++) {
#pragma unroll
        for (int q = 0; q < 8; q++) {
            int e = t + q * 256;
            int k = e >> 5, jj = e & 31;
            tv[k * 33 + jj] = V2[k * N + jbase + c * 32 + jj];
        }
        __syncthreads();
        for (int jj = 0; jj < 32; jj++) {
#pragma unroll
            for (int q = 0; q < 16; q++) {
                int p = t * 16 + q;
                a[q] += tv[(p >> 6) * 33 + jj] * tv[(p & 63) * 33 + jj];
            }
        }
        __syncthreads();
    }
#pragma unroll
    for (int q = 0; q < 16; q++) atomicAdd(&g_G2[t * 16 + q], a[q]);
}

// -------- C = A @ V2^T (atomic across j-splits) + sumsq(A), fused ----------
__global__ __launch_bounds__(256) void k_across(const float* __restrict__ A,
                                                const float* __restrict__ V2) {
    __shared__ float sA[64 * 33];
    __shared__ float sB[32 * 65];
    int t = threadIdx.x;
    int tx = t & 15, ty = t >> 4;
    int i0 = blockIdx.x * 64;
    int jbeg = blockIdx.y * (N / 8);
    int jend = jbeg + (N / 8);
    float acc[16];
#pragma unroll
    for (int q = 0; q < 16; q++) acc[q] = 0.f;
    float ssq = 0.f;
    for (int j0 = jbeg; j0 < jend; j0 += 32) {
#pragma unroll
        for (int q = 0; q < 8; q++) {
            int e = t + q * 256;
            int r = e >> 5, c = e & 31;
            float v = A[(i0 + r) * N + j0 + c];
            sA[r * 33 + c] = v;
            ssq += v * v;
        }
#pragma unroll
        for (int q = 0; q < 8; q++) {
            int e = t + q * 256;
            int k = e >> 5, jj = e & 31;
            sB[jj * 65 + k] = V2[k * N + j0 + jj];
        }
        __syncthreads();
#pragma unroll
        for (int jj = 0; jj < 32; jj++) {
            float av[4], bv[4];
#pragma unroll
            for (int ri = 0; ri < 4; ri++) av[ri] = sA[(ty * 4 + ri) * 33 + jj];
#pragma unroll
            for (int ck = 0; ck < 4; ck++) bv[ck] = sB[jj * 65 + tx * 4 + ck];
#pragma unroll
            for (int ri = 0; ri < 4; ri++)
#pragma unroll
                for (int ck = 0; ck < 4; ck++) acc[ri * 4 + ck] += av[ri] * bv[ck];
        }
        __syncthreads();
    }
#pragma unroll
    for (int ri = 0; ri < 4; ri++)
#pragma unroll
        for (int ck = 0; ck < 4; ck++)
            atomicAdd(&g_C[(i0 + ty * 4 + ri) * S2 + tx * 4 + ck], acc[ri * 4 + ck]);
    float bs = blockReduceSum(ssq);
    if (t == 0) atomicAdd(&g_acc[0], (double)bs);
}

// ---------------- elementwise dot reductions --------------------------------
__global__ void k_dot(int mode) {
    const float *a, *b; int n, outi;
    if (mode == 0) { a = g_G1; b = g_G2; n = S2 * S2; outi = 2; }
    else           { a = g_W2; b = g_C;  n = N * S2;  outi = 1; }
    int tid = blockIdx.x * blockDim.x + threadIdx.x;
    int stride = gridDim.x * blockDim.x;
    float s = 0.f;
    for (int i = tid; i < n; i += stride) s += a[i] * b[i];
    float bs = blockReduceSum(s);
    if (threadIdx.x == 0) atomicAdd(&g_acc[outi], (double)bs);
}

// -------- fused refl_sim tile: hn@hn^T, exp, row totals + sim mask ---------
__global__ __launch_bounds__(256) void k_refl(const float* __restrict__ sim) {
    __shared__ float sI[16 * 65];
    __shared__ float sJ[16 * 65];
    __shared__ float rT[64], rS[64];
    int t = threadIdx.x;
    int tx = t & 15, ty = t >> 4;
    int i0 = blockIdx.y * 64, j0 = blockIdx.x * 64;
    float acc[16];
#pragma unroll
    for (int q = 0; q < 16; q++) acc[q] = 0.f;
    for (int k0 = 0; k0 < S0; k0 += 16) {
#pragma unroll
        for (int q = 0; q < 4; q++) {
            int e = t + q * 256;
            int r = e >> 4, kk = e & 15;
            sI[kk * 65 + r] = g_hn[(i0 + r) * S0 + k0 + kk];
            sJ[kk * 65 + r] = g_hn[(j0 + r) * S0 + k0 + kk];
        }
        __syncthreads();
#pragma unroll
        for (int kk = 0; kk < 16; kk++) {
            float av[4], bv[4];
#pragma unroll
            for (int ri = 0; ri < 4; ri++) av[ri] = sI[kk * 65 + ty * 4 + ri];
#pragma unroll
            for (int cj = 0; cj < 4; cj++) bv[cj] = sJ[kk * 65 + tx * 4 + cj];
#pragma unroll
            for (int ri = 0; ri < 4; ri++)
#pragma unroll
                for (int cj = 0; cj < 4; cj++) acc[ri * 4 + cj] += av[ri] * bv[cj];
        }
        __syncthreads();
    }
    if (t < 64) { rT[t] = 0.f; rS[t] = 0.f; }
    __syncthreads();
#pragma unroll
    for (int ri = 0; ri < 4; ri++) {
        int row = i0 + ty * 4 + ri;
        float4 sv = *reinterpret_cast<const float4*>(sim + row * N + j0 + tx * 4);
        float e0 = __expf(2.f * acc[ri * 4 + 0]);
        float e1 = __expf(2.f * acc[ri * 4 + 1]);
        float e2 = __expf(2.f * acc[ri * 4 + 2]);
        float e3 = __expf(2.f * acc[ri * 4 + 3]);
        float rs = e0 + e1 + e2 + e3;
        float ss = (sv.x > 0.9f ? e0 : 0.f) + (sv.y > 0.9f ? e1 : 0.f)
                 + (sv.z > 0.9f ? e2 : 0.f) + (sv.w > 0.9f ? e3 : 0.f);
        atomicAdd(&rT[ty * 4 + ri], rs);
        atomicAdd(&rS[ty * 4 + ri], ss);
    }
    __syncthreads();
    if (t < 64) {
        atomicAdd(&g_total [i0 + t], rT[t]);
        atomicAdd(&g_possim[i0 + t], rS[t]);
    }
}

// -------- clique / neighbor positive sums via gather (set-dedupe) ----------
__global__ void k_gather(const int* __restrict__ clq, const int* __restrict__ ngh) {
    int tid = blockIdx.x * blockDim.x + threadIdx.x;
    if (tid >= N * 24) return;
    int i = tid / 24, m = tid % 24;
    int j; float* out;
    if (m < 8) {
        j = clq[i * 8 + m];
        for (int p = 0; p < m; p++) if (clq[i * 8 + p] == j) return;  // set semantics
        out = g_posclq;
    } else {
        int mm = m - 8;
        j = ngh[i * 16 + mm];
        for (int p = 0; p < mm; p++) if (ngh[i * 16 + p] == j) return;
        out = g_posngh;
    }
    const float4* hi = reinterpret_cast<const float4*>(g_hn + i * S0);
    const float4* hj = reinterpret_cast<const float4*>(g_hn + j * S0);
    float d = 0.f;
#pragma unroll 8
    for (int s = 0; s < 64; s++) {
        float4 x = hi[s], y = hj[s];
        d += x.x * y.x + x.y * y.y + x.z * y.z + x.w * y.w;
    }
    atomicAdd(&out[i], expf(2.f * d));
}

// ---------------- loss5: sum min(X,0)^2 ------------------------------------
__global__ void k_loss5(const float* __restrict__ X, int n) {
    int tid = blockIdx.x * blockDim.x + threadIdx.x;
    int stride = gridDim.x * blockDim.x;
    float s = 0.f;
    for (int i = tid; i < n; i += stride) {
        float v = X[i];
        if (v < 0.f) s += v * v;
    }
    float bs = blockReduceSum(s);
    if (threadIdx.x == 0) atomicAdd(&g_acc[3], (double)bs);
}

// ---------------- contrastive -log(pos/total) sums --------------------------
__global__ void k_contrast() {
    int tid = blockIdx.x * blockDim.x + threadIdx.x;
    int stride = gridDim.x * blockDim.x;
    float sc = 0.f, sn = 0.f, ssim = 0.f;
    for (int i = tid; i < N; i += stride) {
        float tot = g_total[i];
        float c1 = g_posclq[i] / tot;
        float c2 = g_posngh[i] / tot;
        float c3 = g_possim[i] / tot;
        if (c1 != 0.f) sc   -= logf(c1);
        if (c2 != 0.f) sn   -= logf(c2);
        if (c3 != 0.f) ssim -= logf(c3);
    }
    float b1 = blockReduceSum(sc);
    float b2 = blockReduceSum(sn);
    float b3 = blockReduceSum(ssim);
    if (threadIdx.x == 0) {
        atomicAdd(&g_acc[4], (double)b1);
        atomicAdd(&g_acc[5], (double)b2);
        atomicAdd(&g_acc[6], (double)b3);
    }
}

// ---------------- final combine ---------------------------------------------
__global__ void k_final(float* out) {
    double l1 = g_acc[0] - 2.0 * g_acc[1] + g_acc[2];
    double l2 = g_acc[4] / (double)N;
    double l3 = g_acc[5] / (double)N;
    double l4 = g_acc[6] / (double)N;
    double l5 = g_acc[3];
    double tot = l1 + 0.1 * l2 + 0.1 * l3 + 0.1 * l4 + l5;
    out[0] = (float)tot; out[1] = (float)l1; out[2] = (float)l2;
    out[3] = (float)l3;  out[4] = (float)l4; out[5] = (float)l5;
}

// ---------------- launch -----------------------------------------------------
extern "C" void kernel_launch(void* const* d_in, const int* in_sizes, int n_in,
                              void* d_out, int out_size) {
    const float* A    = (const float*)d_in[0];
    const float* U0   = (const float*)d_in[1];
    const float* U1   = (const float*)d_in[2];
    const float* U2   = (const float*)d_in[3];
    const float* V2   = (const float*)d_in[4];
    const float* fc1w = (const float*)d_in[5];
    const float* fc1b = (const float*)d_in[6];
    const float* fc2w = (const float*)d_in[7];
    const float* fc2b = (const float*)d_in[8];
    const float* sim  = (const float*)d_in[9];
    const int*   clq  = (const int*)d_in[10];
    const int*   ngh  = (const int*)d_in[11];
    float* out = (float*)d_out;

    k_zero<<<256, 256>>>();
    k_factor<<<N, 128>>>(U0, U1, U2);
    k_proj<<<N, 256>>>(V2, fc1w, fc1b, fc2w, fc2b);
    k_gram1<<<32, 256>>>();
    k_gram2<<<32, 256>>>(V2);
    k_across<<<dim3(64, 8), 256>>>(A, V2);
    k_dot<<<64, 256>>>(0);
    k_dot<<<64, 256>>>(1);
    k_refl<<<dim3(64, 64), 256>>>(sim);
    k_gather<<<(N * 24 + 255) / 256, 256>>>(clq, ngh);
    k_loss5<<<64, 256>>>(U0, N * S0);
    k_loss5<<<64, 256>>>(U1, S0 * S1);
    k_loss5<<<64, 256>>>(U2, S1 * S2);
    k_loss5<<<64, 256>>>(V2, S2 * N);
    k_contrast<<<32, 256>>>();
    k_final<<<1, 1>>>(out);
}

// round 5
// speedup vs baseline: 1.3572x; 1.3572x over previous
#include <cuda_runtime.h>
#include <math.h>

#define N   4096
#define S0  256
#define S1  128
#define S2  64
#define RPAD 36

// ---------------- scratch (device globals; no allocations allowed) ----------
__device__ __align__(16) float g_W2[N * S2];     // (U0@U1)@U2            [N,64]
__device__ __align__(16) float g_Cp[4][N * S2];  // A @ V2^T partials     [N,64]
__device__ __align__(16) float g_hn[N * S0];     // row-normalized h      [N,256]
__device__ float g_G1[S2 * S2];                  // W2^T W2
__device__ float g_G2[S2 * S2];                  // V2 V2^T
__device__ float g_total [N];
__device__ float g_possim[N];
__device__ float g_posclq[N];
__device__ float g_posngh[N];
// 0: sumsq(A)  1: <W2, A V2^T>  2: <G1,G2>  3: loss5
// 4: clique -log sum  5: neighbor -log sum  6: sim -log sum
__device__ double g_acc[8];

// ---------------- helpers ---------------------------------------------------
__device__ __forceinline__ float blockReduceSum(float v) {
    __shared__ float sh[33];
    int lane = threadIdx.x & 31, w = threadIdx.x >> 5;
#pragma unroll
    for (int o = 16; o; o >>= 1) v += __shfl_down_sync(0xffffffffu, v, o);
    if (lane == 0) sh[w] = v;
    __syncthreads();
    if (threadIdx.x == 0) {
        int nw = (blockDim.x + 31) >> 5;
        float r = 0.f;
        for (int x = 0; x < nw; x++) r += sh[x];
        sh[32] = r;
    }
    __syncthreads();
    float r = sh[32];
    __syncthreads();
    return r;
}

__device__ __forceinline__ unsigned f2tf32(float x) {
    unsigned r;
    asm("cvt.rna.tf32.f32 %0, %1;" : "=r"(r) : "f"(x));
    return r;
}

__device__ __forceinline__ void mma_tf32(float* c,
                                         unsigned a0, unsigned a1, unsigned a2, unsigned a3,
                                         unsigned b0, unsigned b1) {
    asm volatile(
        "mma.sync.aligned.m16n8k8.row.col.f32.tf32.tf32.f32 "
        "{%0,%1,%2,%3},{%4,%5,%6,%7},{%8,%9},{%0,%1,%2,%3};"
        : "+f"(c[0]), "+f"(c[1]), "+f"(c[2]), "+f"(c[3])
        : "r"(a0), "r"(a1), "r"(a2), "r"(a3), "r"(b0), "r"(b1));
}

// ---------------- zero scratch ----------------------------------------------
__global__ void k_zero() {
    int tid = blockIdx.x * blockDim.x + threadIdx.x;
    int stride = gridDim.x * blockDim.x;
    for (int i = tid; i < S2 * S2; i += stride) { g_G1[i] = 0.f; g_G2[i] = 0.f; }
    for (int i = tid; i < N; i += stride) {
        g_total[i] = 0.f; g_possim[i] = 0.f; g_posclq[i] = 0.f; g_posngh[i] = 0.f;
    }
    if (tid < 8) g_acc[tid] = 0.0;
}

// ---------------- W2 = (U0 @ U1) @ U2, one block per row -------------------
__global__ __launch_bounds__(128) void k_factor(const float* __restrict__ U0,
                                                const float* __restrict__ U1,
                                                const float* __restrict__ U2) {
    __shared__ float sU0[S0];
    __shared__ float sW1[S1];
    int i = blockIdx.x, t = threadIdx.x;
    sU0[t]       = U0[i * S0 + t];
    sU0[t + 128] = U0[i * S0 + t + 128];
    __syncthreads();
    float acc = 0.f;
#pragma unroll 8
    for (int k = 0; k < S0; k++) acc += sU0[k] * U1[k * S1 + t];
    sW1[t] = acc;
    __syncthreads();
    if (t < S2) {
        float a = 0.f;
#pragma unroll 8
        for (int k = 0; k < S1; k++) a += sW1[k] * U2[k * S2 + t];
        g_W2[i * S2 + t] = a;
    }
}

// ------------ hn = l2norm_rows( elu(V2^T fc1^T + b1) fc2^T + b2 ) ----------
__global__ __launch_bounds__(256) void k_proj(const float* __restrict__ V2,
                                              const float* __restrict__ fc1w,
                                              const float* __restrict__ fc1b,
                                              const float* __restrict__ fc2w,
                                              const float* __restrict__ fc2b) {
    __shared__ float sV[S2];
    __shared__ float sH1[S1];
    int n = blockIdx.x, t = threadIdx.x;
    if (t < S2) sV[t] = V2[t * N + n];
    __syncthreads();
    if (t < S1) {
        float a = fc1b[t];
#pragma unroll 8
        for (int s = 0; s < S2; s++) a += sV[s] * fc1w[t * S2 + s];
        sH1[t] = (a > 0.f) ? a : expm1f(a);   // elu, alpha=1
    }
    __syncthreads();
    float a = fc2b[t];
#pragma unroll 8
    for (int s = 0; s < S1; s++) a += sH1[s] * fc2w[t * S1 + s];
    float ss = blockReduceSum(a * a);
    float inv = 1.f / fmaxf(sqrtf(ss), 1e-12f);
    g_hn[n * S0 + t] = a * inv;
}

// ---------------- G1 = W2^T W2 (64x64) --------------------------------------
__global__ __launch_bounds__(256) void k_gram1() {
    __shared__ float tw[32 * 65];
    int t = threadIdx.x;
    float a[16];
#pragma unroll
    for (int q = 0; q < 16; q++) a[q] = 0.f;
    int base = blockIdx.x * 64;   // 64 blocks * 64 rows = 4096
    for (int c = 0; c < 2; c++) {
#pragma unroll
        for (int q = 0; q < 8; q++) {
            int e = t + q * 256;
            int r = e >> 6, k = e & 63;
            tw[r * 65 + k] = g_W2[(base + c * 32 + r) * S2 + k];
        }
        __syncthreads();
        for (int r = 0; r < 32; r++) {
#pragma unroll
            for (int q = 0; q < 16; q++) {
                int p = t * 16 + q;
                a[q] += tw[r * 65 + (p >> 6)] * tw[r * 65 + (p & 63)];
            }
        }
        __syncthreads();
    }
#pragma unroll
    for (int q = 0; q < 16; q++) atomicAdd(&g_G1[t * 16 + q], a[q]);
}

// ---------------- G2 = V2 V2^T (64x64) --------------------------------------
__global__ __launch_bounds__(256) void k_gram2(const float* __restrict__ V2) {
    __shared__ float tv[S2 * 33];
    int t = threadIdx.x;
    float a[16];
#pragma unroll
    for (int q = 0; q < 16; q++) a[q] = 0.f;
    int jbase = blockIdx.x * 64;  // 64 blocks * 64 cols = 4096
    for (int c = 0; c < 2; c++) {
#pragma unroll
        for (int q = 0; q < 8; q++) {
            int e = t + q * 256;
            int k = e >> 5, jj = e & 31;
            tv[k * 33 + jj] = V2[k * N + jbase + c * 32 + jj];
        }
        __syncthreads();
        for (int jj = 0; jj < 32; jj++) {
#pragma unroll
            for (int q = 0; q < 16; q++) {
                int p = t * 16 + q;
                a[q] += tv[(p >> 6) * 33 + jj] * tv[(p & 63) * 33 + jj];
            }
        }
        __syncthreads();
    }
#pragma unroll
    for (int q = 0; q < 16; q++) atomicAdd(&g_G2[t * 16 + q], a[q]);
}

// -------- C = A @ V2^T via tf32 mma (+ fused sumsq(A)) ----------------------
// grid (32, 4): 128-row i tiles, 4 splits over j (k-dim). Each split writes
// its own partial buffer g_Cp[split] with plain stores (no atomics).
__global__ __launch_bounds__(256) void k_across(const float* __restrict__ A,
                                                const float* __restrict__ V2) {
    __shared__ unsigned sA[128 * RPAD];
    __shared__ unsigned sV[S2 * RPAD];
    int t = threadIdx.x;
    int lane = t & 31, warp = t >> 5;
    int wi = warp >> 1, ws = warp & 1;          // 4 x 2 warp grid
    int g = lane >> 2, q4 = lane & 3;
    int i0 = blockIdx.x * 128;
    int jbeg = blockIdx.y * (N / 4);
    int jend = jbeg + (N / 4);

    float acc[2][4][4];
#pragma unroll
    for (int m = 0; m < 2; m++)
#pragma unroll
        for (int n = 0; n < 4; n++)
#pragma unroll
            for (int q = 0; q < 4; q++) acc[m][n][q] = 0.f;
    float ssq = 0.f;

    int lrow = t >> 1, lhalf = t & 1;
    for (int j0 = jbeg; j0 < jend; j0 += 32) {
        // A tile 128x32
#pragma unroll
        for (int q = 0; q < 4; q++) {
            int c = lhalf * 16 + q * 4;
            float4 v = *reinterpret_cast<const float4*>(A + (i0 + lrow) * N + j0 + c);
            ssq += v.x * v.x + v.y * v.y + v.z * v.z + v.w * v.w;
            sA[lrow * RPAD + c + 0] = f2tf32(v.x);
            sA[lrow * RPAD + c + 1] = f2tf32(v.y);
            sA[lrow * RPAD + c + 2] = f2tf32(v.z);
            sA[lrow * RPAD + c + 3] = f2tf32(v.w);
        }
        // V tile: sV[s][k] = V2[s*N + j0 + k], 64x32
#pragma unroll
        for (int q = 0; q < 2; q++) {
            int e = t * 2 + q;          // 512 float4 slots
            int r = e >> 3, c = (e & 7) * 4;
            float4 v = *reinterpret_cast<const float4*>(V2 + r * N + j0 + c);
            sV[r * RPAD + c + 0] = f2tf32(v.x);
            sV[r * RPAD + c + 1] = f2tf32(v.y);
            sV[r * RPAD + c + 2] = f2tf32(v.z);
            sV[r * RPAD + c + 3] = f2tf32(v.w);
        }
        __syncthreads();
#pragma unroll
        for (int ks = 0; ks < 4; ks++) {
            int kk = ks * 8;
            unsigned a[2][4], b[4][2];
#pragma unroll
            for (int m = 0; m < 2; m++) {
                int r = wi * 32 + m * 16;
                a[m][0] = sA[(r + g) * RPAD + kk + q4];
                a[m][1] = sA[(r + g + 8) * RPAD + kk + q4];
                a[m][2] = sA[(r + g) * RPAD + kk + q4 + 4];
                a[m][3] = sA[(r + g + 8) * RPAD + kk + q4 + 4];
            }
#pragma unroll
            for (int n = 0; n < 4; n++) {
                int c = ws * 32 + n * 8;
                b[n][0] = sV[(c + g) * RPAD + kk + q4];
                b[n][1] = sV[(c + g) * RPAD + kk + q4 + 4];
            }
#pragma unroll
            for (int m = 0; m < 2; m++)
#pragma unroll
                for (int n = 0; n < 4; n++)
                    mma_tf32(acc[m][n], a[m][0], a[m][1], a[m][2], a[m][3],
                             b[n][0], b[n][1]);
        }
        __syncthreads();
    }
    // store partials (plain float2 stores; every element of this split written)
    float* out = g_Cp[blockIdx.y];
#pragma unroll
    for (int m = 0; m < 2; m++) {
        int r0 = i0 + wi * 32 + m * 16 + g;
#pragma unroll
        for (int n = 0; n < 4; n++) {
            int c = ws * 32 + n * 8 + q4 * 2;
            *reinterpret_cast<float2*>(out + r0 * S2 + c)       = make_float2(acc[m][n][0], acc[m][n][1]);
            *reinterpret_cast<float2*>(out + (r0 + 8) * S2 + c) = make_float2(acc[m][n][2], acc[m][n][3]);
        }
    }
    float bs = blockReduceSum(ssq);
    if (t == 0) atomicAdd(&g_acc[0], (double)bs);
}

// ---------------- elementwise dot reductions --------------------------------
__global__ void k_dot(int mode) {
    int tid = blockIdx.x * blockDim.x + threadIdx.x;
    int stride = gridDim.x * blockDim.x;
    float s = 0.f;
    if (mode == 0) {
        for (int i = tid; i < S2 * S2; i += stride) s += g_G1[i] * g_G2[i];
    } else {
        for (int i = tid; i < N * S2; i += stride)
            s += g_W2[i] * (g_Cp[0][i] + g_Cp[1][i] + g_Cp[2][i] + g_Cp[3][i]);
    }
    float bs = blockReduceSum(s);
    if (threadIdx.x == 0) atomicAdd(&g_acc[mode == 0 ? 2 : 1], (double)bs);
}

// -------- fused refl_sim tile via tf32 mma: 128x128 per block ---------------
__global__ __launch_bounds__(256) void k_refl(const float* __restrict__ sim) {
    __shared__ unsigned sI[128 * RPAD];
    __shared__ unsigned sJ[128 * RPAD];
    int t = threadIdx.x;
    int lane = t & 31, warp = t >> 5;
    int wi = warp >> 1, wj = warp & 1;          // 4 x 2 warp grid
    int g = lane >> 2, q4 = lane & 3;
    int i0 = blockIdx.y * 128, j0 = blockIdx.x * 128;

    float acc[2][8][4];
#pragma unroll
    for (int m = 0; m < 2; m++)
#pragma unroll
        for (int n = 0; n < 8; n++)
#pragma unroll
            for (int q = 0; q < 4; q++) acc[m][n][q] = 0.f;

    int lrow = t >> 1, lhalf = t & 1;
    for (int k0 = 0; k0 < S0; k0 += 32) {
#pragma unroll
        for (int q = 0; q < 4; q++) {
            int c = lhalf * 16 + q * 4;
            float4 v = *reinterpret_cast<const float4*>(g_hn + (i0 + lrow) * S0 + k0 + c);
            sI[lrow * RPAD + c + 0] = f2tf32(v.x);
            sI[lrow * RPAD + c + 1] = f2tf32(v.y);
            sI[lrow * RPAD + c + 2] = f2tf32(v.z);
            sI[lrow * RPAD + c + 3] = f2tf32(v.w);
            float4 w = *reinterpret_cast<const float4*>(g_hn + (j0 + lrow) * S0 + k0 + c);
            sJ[lrow * RPAD + c + 0] = f2tf32(w.x);
            sJ[lrow * RPAD + c + 1] = f2tf32(w.y);
            sJ[lrow * RPAD + c + 2] = f2tf32(w.z);
            sJ[lrow * RPAD + c + 3] = f2tf32(w.w);
        }
        __syncthreads();
#pragma unroll
        for (int ks = 0; ks < 4; ks++) {
            int kk = ks * 8;
            unsigned a[2][4], b[8][2];
#pragma unroll
            for (int m = 0; m < 2; m++) {
                int r = wi * 32 + m * 16;
                a[m][0] = sI[(r + g) * RPAD + kk + q4];
                a[m][1] = sI[(r + g + 8) * RPAD + kk + q4];
                a[m][2] = sI[(r + g) * RPAD + kk + q4 + 4];
                a[m][3] = sI[(r + g + 8) * RPAD + kk + q4 + 4];
            }
#pragma unroll
            for (int n = 0; n < 8; n++) {
                int c = wj * 64 + n * 8;
                b[n][0] = sJ[(c + g) * RPAD + kk + q4];
                b[n][1] = sJ[(c + g) * RPAD + kk + q4 + 4];
            }
#pragma unroll
            for (int m = 0; m < 2; m++)
#pragma unroll
                for (int n = 0; n < 8; n++)
                    mma_tf32(acc[m][n], a[m][0], a[m][1], a[m][2], a[m][3],
                             b[n][0], b[n][1]);
        }
        __syncthreads();
    }

    // epilogue: exp, row totals + sim-thresholded totals
#pragma unroll
    for (int m = 0; m < 2; m++) {
        float rs0 = 0.f, rs1 = 0.f, rp0 = 0.f, rp1 = 0.f;
        int r0 = i0 + wi * 32 + m * 16 + g;
#pragma unroll
        for (int n = 0; n < 8; n++) {
            int c = j0 + wj * 64 + n * 8 + q4 * 2;
            float2 s0 = *reinterpret_cast<const float2*>(sim + r0 * N + c);
            float2 s1 = *reinterpret_cast<const float2*>(sim + (r0 + 8) * N + c);
            float e0 = __expf(2.f * acc[m][n][0]);
            float e1 = __expf(2.f * acc[m][n][1]);
            float e2 = __expf(2.f * acc[m][n][2]);
            float e3 = __expf(2.f * acc[m][n][3]);
            rs0 += e0 + e1;
            rs1 += e2 + e3;
            rp0 += (s0.x > 0.9f ? e0 : 0.f) + (s0.y > 0.9f ? e1 : 0.f);
            rp1 += (s1.x > 0.9f ? e2 : 0.f) + (s1.y > 0.9f ? e3 : 0.f);
        }
        // reduce within quad (lanes sharing the same row)
        rs0 += __shfl_xor_sync(0xffffffffu, rs0, 1);
        rs0 += __shfl_xor_sync(0xffffffffu, rs0, 2);
        rs1 += __shfl_xor_sync(0xffffffffu, rs1, 1);
        rs1 += __shfl_xor_sync(0xffffffffu, rs1, 2);
        rp0 += __shfl_xor_sync(0xffffffffu, rp0, 1);
        rp0 += __shfl_xor_sync(0xffffffffu, rp0, 2);
        rp1 += __shfl_xor_sync(0xffffffffu, rp1, 1);
        rp1 += __shfl_xor_sync(0xffffffffu, rp1, 2);
        if (q4 == 0) {
            atomicAdd(&g_total [r0],     rs0);
            atomicAdd(&g_possim[r0],     rp0);
            atomicAdd(&g_total [r0 + 8], rs1);
            atomicAdd(&g_possim[r0 + 8], rp1);
        }
    }
}

// -------- clique / neighbor positive sums via gather (set-dedupe) ----------
__global__ void k_gather(const int* __restrict__ clq, const int* __restrict__ ngh) {
    int tid = blockIdx.x * blockDim.x + threadIdx.x;
    if (tid >= N * 24) return;
    int i = tid / 24, m = tid % 24;
    int j; float* out;
    if (m < 8) {
        j = clq[i * 8 + m];
        for (int p = 0; p < m; p++) if (clq[i * 8 + p] == j) return;  // set semantics
        out = g_posclq;
    } else {
        int mm = m - 8;
        j = ngh[i * 16 + mm];
        for (int p = 0; p < mm; p++) if (ngh[i * 16 + p] == j) return;
        out = g_posngh;
    }
    const float4* hi = reinterpret_cast<const float4*>(g_hn + i * S0);
    const float4* hj = reinterpret_cast<const float4*>(g_hn + j * S0);
    float d = 0.f;
#pragma unroll 8
    for (int s = 0; s < 64; s++) {
        float4 x = hi[s], y = hj[s];
        d += x.x * y.x + x.y * y.y + x.z * y.z + x.w * y.w;
    }
    atomicAdd(&out[i], expf(2.f * d));
}

// ---------------- loss5: sum min(X,0)^2 ------------------------------------
__global__ void k_loss5(const float* __restrict__ X, int n) {
    int tid = blockIdx.x * blockDim.x + threadIdx.x;
    int stride = gridDim.x * blockDim.x;
    float s = 0.f;
    for (int i = tid; i < n; i += stride) {
        float v = X[i];
        if (v < 0.f) s += v * v;
    }
    float bs = blockReduceSum(s);
    if (threadIdx.x == 0) atomicAdd(&g_acc[3], (double)bs);
}

// ---------------- contrastive -log(pos/total) sums --------------------------
__global__ void k_contrast() {
    int tid = blockIdx.x * blockDim.x + threadIdx.x;
    int stride = gridDim.x * blockDim.x;
    float sc = 0.f, sn = 0.f, ssim = 0.f;
    for (int i = tid; i < N; i += stride) {
        float tot = g_total[i];
        float c1 = g_posclq[i] / tot;
        float c2 = g_posngh[i] / tot;
        float c3 = g_possim[i] / tot;
        if (c1 != 0.f) sc   -= logf(c1);
        if (c2 != 0.f) sn   -= logf(c2);
        if (c3 != 0.f) ssim -= logf(c3);
    }
    float b1 = blockReduceSum(sc);
    float b2 = blockReduceSum(sn);
    float b3 = blockReduceSum(ssim);
    if (threadIdx.x == 0) {
        atomicAdd(&g_acc[4], (double)b1);
        atomicAdd(&g_acc[5], (double)b2);
        atomicAdd(&g_acc[6], (double)b3);
    }
}

// ---------------- final combine ---------------------------------------------
__global__ void k_final(float* out) {
    double l1 = g_acc[0] - 2.0 * g_acc[1] + g_acc[2];
    double l2 = g_acc[4] / (double)N;
    double l3 = g_acc[5] / (double)N;
    double l4 = g_acc[6] / (double)N;
    double l5 = g_acc[3];
    double tot = l1 + 0.1 * l2 + 0.1 * l3 + 0.1 * l4 + l5;
    out[0] = (float)tot; out[1] = (float)l1; out[2] = (float)l2;
    out[3] = (float)l3;  out[4] = (float)l4; out[5] = (float)l5;
}

// ---------------- launch -----------------------------------------------------
extern "C" void kernel_launch(void* const* d_in, const int* in_sizes, int n_in,
                              void* d_out, int out_size) {
    const float* A    = (const float*)d_in[0];
    const float* U0   = (const float*)d_in[1];
    const float* U1   = (const float*)d_in[2];
    const float* U2   = (const float*)d_in[3];
    const float* V2   = (const float*)d_in[4];
    const float* fc1w = (const float*)d_in[5];
    const float* fc1b = (const float*)d_in[6];
    const float* fc2w = (const float*)d_in[7];
    const float* fc2b = (const float*)d_in[8];
    const float* sim  = (const float*)d_in[9];
    const int*   clq  = (const int*)d_in[10];
    const int*   ngh  = (const int*)d_in[11];
    float* out = (float*)d_out;

    k_zero<<<256, 256>>>();
    k_factor<<<N, 128>>>(U0, U1, U2);
    k_proj<<<N, 256>>>(V2, fc1w, fc1b, fc2w, fc2b);
    k_gram1<<<64, 256>>>();
    k_gram2<<<64, 256>>>(V2);
    k_across<<<dim3(32, 4), 256>>>(A, V2);
    k_dot<<<64, 256>>>(0);
    k_dot<<<64, 256>>>(1);
    k_refl<<<dim3(32, 32), 256>>>(sim);
    k_gather<<<(N * 24 + 255) / 256, 256>>>(clq, ngh);
    k_loss5<<<64, 256>>>(U0, N * S0);
    k_loss5<<<64, 256>>>(U1, S0 * S1);
    k_loss5<<<64, 256>>>(U2, S1 * S2);
    k_loss5<<<64, 256>>>(V2, S2 * N);
    k_contrast<<<32, 256>>>();
    k_final<<<1, 1>>>(out);
}

// round 6
// speedup vs baseline: 4.7382x; 3.4910x over previous
#include <cuda_runtime.h>
#include <math.h>

#define N   4096
#define S0  256
#define S1  128
#define S2  64
#define RPAD 36

// ---------------- scratch (device globals; no allocations allowed) ----------
__device__ __align__(16) float g_W2[N * S2];     // (U0@U1)@U2            [N,64]
__device__ __align__(16) float g_Cp[8][N * S2];  // A @ V2^T partials     [N,64]
__device__ __align__(16) float g_hn[N * S0];     // row-normalized h      [N,256]
__device__ float g_G1[S2 * S2];                  // W2^T W2
__device__ float g_G2[S2 * S2];                  // V2 V2^T
__device__ float g_total [N];
__device__ float g_possim[N];
__device__ float g_posclq[N];
__device__ float g_posngh[N];
// 0: sumsq(A)  1: <W2, A V2^T>  2: <G1,G2>  3: loss5
// 4: clique -log sum  5: neighbor -log sum  6: sim -log sum
__device__ double g_acc[8];

// ---------------- helpers ---------------------------------------------------
__device__ __forceinline__ float blockReduceSum(float v) {
    __shared__ float sh[33];
    int lane = threadIdx.x & 31, w = threadIdx.x >> 5;
#pragma unroll
    for (int o = 16; o; o >>= 1) v += __shfl_down_sync(0xffffffffu, v, o);
    if (lane == 0) sh[w] = v;
    __syncthreads();
    if (threadIdx.x == 0) {
        int nw = (blockDim.x + 31) >> 5;
        float r = 0.f;
        for (int x = 0; x < nw; x++) r += sh[x];
        sh[32] = r;
    }
    __syncthreads();
    float r = sh[32];
    __syncthreads();
    return r;
}

__device__ __forceinline__ unsigned f2tf32(float x) {
    unsigned r;
    asm("cvt.rna.tf32.f32 %0, %1;" : "=r"(r) : "f"(x));
    return r;
}

__device__ __forceinline__ void mma_tf32(float* c,
                                         unsigned a0, unsigned a1, unsigned a2, unsigned a3,
                                         unsigned b0, unsigned b1) {
    asm volatile(
        "mma.sync.aligned.m16n8k8.row.col.f32.tf32.tf32.f32 "
        "{%0,%1,%2,%3},{%4,%5,%6,%7},{%8,%9},{%0,%1,%2,%3};"
        : "+f"(c[0]), "+f"(c[1]), "+f"(c[2]), "+f"(c[3])
        : "r"(a0), "r"(a1), "r"(a2), "r"(a3), "r"(b0), "r"(b1));
}

// ---------------- zero scratch ----------------------------------------------
__global__ void k_zero() {
    int tid = blockIdx.x * blockDim.x + threadIdx.x;
    int stride = gridDim.x * blockDim.x;
    for (int i = tid; i < S2 * S2; i += stride) { g_G1[i] = 0.f; g_G2[i] = 0.f; }
    for (int i = tid; i < N; i += stride) {
        g_total[i] = 0.f; g_possim[i] = 0.f; g_posclq[i] = 0.f; g_posngh[i] = 0.f;
    }
    if (tid < 8) g_acc[tid] = 0.0;
}

// -------- W2 = (U0 @ U1) @ U2, 16 rows per block, U1 staged via smem --------
__global__ __launch_bounds__(256) void k_factor(const float* __restrict__ U0,
                                                const float* __restrict__ U1,
                                                const float* __restrict__ U2) {
    __shared__ float sU0[16 * 256];
    __shared__ float sU1[32 * 132];
    __shared__ float sW1[16 * 132];
    int t = threadIdx.x;
    int i0 = blockIdx.x * 16;
    // load U0 tile [16][256]
#pragma unroll
    for (int q = 0; q < 16; q++) {
        int e = t + q * 256;
        int r = e >> 8, k = e & 255;
        sU0[r * 256 + k] = U0[(i0 + r) * S0 + k];
    }
    // phase 1: W1[16][128]
    int ty = t >> 5, tx = t & 31;       // n = ty*2, j = tx*4
    float accw[2][4];
#pragma unroll
    for (int i = 0; i < 2; i++)
#pragma unroll
        for (int k = 0; k < 4; k++) accw[i][k] = 0.f;
    for (int k0 = 0; k0 < S0; k0 += 32) {
        __syncthreads();
#pragma unroll
        for (int q = 0; q < 16; q++) {
            int e = t + q * 256;
            int kk = e >> 7, j = e & 127;
            sU1[kk * 132 + j] = U1[(k0 + kk) * S1 + j];
        }
        __syncthreads();
#pragma unroll
        for (int kk = 0; kk < 32; kk++) {
            float4 b = *reinterpret_cast<const float4*>(&sU1[kk * 132 + tx * 4]);
            float a0 = sU0[(ty * 2 + 0) * 256 + k0 + kk];
            float a1 = sU0[(ty * 2 + 1) * 256 + k0 + kk];
            accw[0][0] += a0 * b.x; accw[0][1] += a0 * b.y;
            accw[0][2] += a0 * b.z; accw[0][3] += a0 * b.w;
            accw[1][0] += a1 * b.x; accw[1][1] += a1 * b.y;
            accw[1][2] += a1 * b.z; accw[1][3] += a1 * b.w;
        }
    }
    __syncthreads();
#pragma unroll
    for (int i = 0; i < 2; i++)
        *reinterpret_cast<float4*>(&sW1[(ty * 2 + i) * 132 + tx * 4]) =
            make_float4(accw[i][0], accw[i][1], accw[i][2], accw[i][3]);
    __syncthreads();
    // phase 2: W2[16][64]
    int tn = t >> 4, tc = t & 15;       // n = tn, c = tc*4
    float acc2[4] = {0.f, 0.f, 0.f, 0.f};
#pragma unroll 4
    for (int k = 0; k < S1; k++) {
        float a = sW1[tn * 132 + k];
        float4 b = *reinterpret_cast<const float4*>(&U2[k * S2 + tc * 4]);
        acc2[0] += a * b.x; acc2[1] += a * b.y;
        acc2[2] += a * b.z; acc2[3] += a * b.w;
    }
    *reinterpret_cast<float4*>(&g_W2[(i0 + tn) * S2 + tc * 4]) =
        make_float4(acc2[0], acc2[1], acc2[2], acc2[3]);
}

// ------------ hn = l2norm_rows( elu(V2^T fc1^T + b1) fc2^T + b2 ) ----------
// 32-node tile per block, all weight access through coalesced smem staging.
// dynamic smem layout (floats):
//   [0 .. 2560)        sXT  [64 s][40]   (stage 1)   } aliased with
//   [2560 .. 11008)    sW1T [64 s][132]  (stage 1)   } sW2T [128 j][132] stage 2
//   [16896 .. 21120)   sH1  [32 n][132]
#define PROJ_SMEM_FLOATS 21120
__global__ __launch_bounds__(256) void k_proj(const float* __restrict__ V2,
                                              const float* __restrict__ fc1w,
                                              const float* __restrict__ fc1b,
                                              const float* __restrict__ fc2w,
                                              const float* __restrict__ fc2b) {
    extern __shared__ float dsm[];
    float* sXT  = dsm;           // [64][40]
    float* sW1T = dsm + 2560;    // [64][132]
    float* sW2T = dsm;           // [128][132] (stage 2, aliases stage-1 arrays)
    float* sH1  = dsm + 16896;   // [32][132]
    int t = threadIdx.x;
    int n0 = blockIdx.x * 32;
    int ty = t >> 5, tx = t & 31;     // n = ty*4 (4 rows), j/t = tx*4 (4 cols)

    // load X^T tile: sXT[s][n] = V2[s*N + n0+n]
#pragma unroll
    for (int q = 0; q < 8; q++) {
        int e = t + q * 256;
        int s = e >> 5, n = e & 31;
        sXT[s * 40 + n] = V2[s * N + n0 + n];
    }
    // transpose fc1w into sW1T[s][j]
#pragma unroll
    for (int q = 0; q < 32; q++) {
        int e = t + q * 256;
        int j = e >> 6, s = e & 63;
        sW1T[s * 132 + j] = fc1w[e];
    }
    __syncthreads();

    // stage 1: H1[n][j] = elu(b1[j] + sum_s X[n][s] W1[j][s])
    float4 b1v = *reinterpret_cast<const float4*>(&fc1b[tx * 4]);
    float acc1[4][4];
#pragma unroll
    for (int i = 0; i < 4; i++) {
        acc1[i][0] = b1v.x; acc1[i][1] = b1v.y;
        acc1[i][2] = b1v.z; acc1[i][3] = b1v.w;
    }
#pragma unroll 4
    for (int s = 0; s < S2; s++) {
        float4 a = *reinterpret_cast<const float4*>(&sXT[s * 40 + ty * 4]);
        float4 b = *reinterpret_cast<const float4*>(&sW1T[s * 132 + tx * 4]);
        float av[4] = {a.x, a.y, a.z, a.w};
#pragma unroll
        for (int i = 0; i < 4; i++) {
            acc1[i][0] += av[i] * b.x; acc1[i][1] += av[i] * b.y;
            acc1[i][2] += av[i] * b.z; acc1[i][3] += av[i] * b.w;
        }
    }
#pragma unroll
    for (int i = 0; i < 4; i++) {
        float4 h;
        h.x = acc1[i][0] > 0.f ? acc1[i][0] : expm1f(acc1[i][0]);
        h.y = acc1[i][1] > 0.f ? acc1[i][1] : expm1f(acc1[i][1]);
        h.z = acc1[i][2] > 0.f ? acc1[i][2] : expm1f(acc1[i][2]);
        h.w = acc1[i][3] > 0.f ? acc1[i][3] : expm1f(acc1[i][3]);
        *reinterpret_cast<float4*>(&sH1[(ty * 4 + i) * 132 + tx * 4]) = h;
    }

    // stage 2: H[n][t] = b2[t] + sum_j H1[n][j] W2[t][j], 2 chunks of 128 t
    float h[2][4][4];
#pragma unroll
    for (int c = 0; c < 2; c++) {
        __syncthreads();
        // transpose fc2w chunk into sW2T[j][lt]
#pragma unroll
        for (int q = 0; q < 64; q++) {
            int e = t + q * 256;
            int lt = e >> 7, j = e & 127;
            sW2T[j * 132 + lt] = fc2w[(c * 128 + lt) * S1 + j];
        }
        __syncthreads();
        float4 b2v = *reinterpret_cast<const float4*>(&fc2b[c * 128 + tx * 4]);
#pragma unroll
        for (int i = 0; i < 4; i++) {
            h[c][i][0] = b2v.x; h[c][i][1] = b2v.y;
            h[c][i][2] = b2v.z; h[c][i][3] = b2v.w;
        }
#pragma unroll 4
        for (int j = 0; j < S1; j++) {
            float4 b = *reinterpret_cast<const float4*>(&sW2T[j * 132 + tx * 4]);
#pragma unroll
            for (int i = 0; i < 4; i++) {
                float a = sH1[(ty * 4 + i) * 132 + j];
                h[c][i][0] += a * b.x; h[c][i][1] += a * b.y;
                h[c][i][2] += a * b.z; h[c][i][3] += a * b.w;
            }
        }
    }
    // row norms: all 32 lanes of a warp share the same 4 rows
#pragma unroll
    for (int i = 0; i < 4; i++) {
        float ss = 0.f;
#pragma unroll
        for (int c = 0; c < 2; c++)
#pragma unroll
            for (int k = 0; k < 4; k++) ss += h[c][i][k] * h[c][i][k];
#pragma unroll
        for (int o = 16; o; o >>= 1) ss += __shfl_xor_sync(0xffffffffu, ss, o);
        float inv = 1.f / fmaxf(sqrtf(ss), 1e-12f);
        int row = n0 + ty * 4 + i;
#pragma unroll
        for (int c = 0; c < 2; c++)
            *reinterpret_cast<float4*>(&g_hn[row * S0 + c * 128 + tx * 4]) =
                make_float4(h[c][i][0] * inv, h[c][i][1] * inv,
                            h[c][i][2] * inv, h[c][i][3] * inv);
    }
}

// ---------------- G1 = W2^T W2 (64x64), 64 k-rows per block -----------------
__global__ __launch_bounds__(256) void k_gram1() {
    __shared__ float sT[64 * 68];
    int t = threadIdx.x;
    int k0 = blockIdx.x * 64;
#pragma unroll
    for (int q = 0; q < 16; q++) {
        int e = t + q * 256;
        int r = e >> 6, c = e & 63;
        sT[r * 68 + c] = g_W2[(k0 + r) * S2 + c];
    }
    __syncthreads();
    int a = (t >> 4) * 4, b = (t & 15) * 4;
    float acc[4][4];
#pragma unroll
    for (int i = 0; i < 4; i++)
#pragma unroll
        for (int k = 0; k < 4; k++) acc[i][k] = 0.f;
#pragma unroll 4
    for (int r = 0; r < 64; r++) {
        float4 va = *reinterpret_cast<const float4*>(&sT[r * 68 + a]);
        float4 vb = *reinterpret_cast<const float4*>(&sT[r * 68 + b]);
        float av[4] = {va.x, va.y, va.z, va.w};
#pragma unroll
        for (int i = 0; i < 4; i++) {
            acc[i][0] += av[i] * vb.x; acc[i][1] += av[i] * vb.y;
            acc[i][2] += av[i] * vb.z; acc[i][3] += av[i] * vb.w;
        }
    }
#pragma unroll
    for (int i = 0; i < 4; i++)
#pragma unroll
        for (int k = 0; k < 4; k++)
            atomicAdd(&g_G1[(a + i) * S2 + b + k], acc[i][k]);
}

// ---------------- G2 = V2 V2^T (64x64), 64 j-cols per block -----------------
__global__ __launch_bounds__(256) void k_gram2(const float* __restrict__ V2) {
    __shared__ float sT[64 * 68];   // sT[j][s]
    int t = threadIdx.x;
    int j0 = blockIdx.x * 64;
#pragma unroll
    for (int q = 0; q < 16; q++) {
        int e = t + q * 256;
        int s = e >> 6, j = e & 63;
        sT[j * 68 + s] = V2[s * N + j0 + j];
    }
    __syncthreads();
    int a = (t >> 4) * 4, b = (t & 15) * 4;
    float acc[4][4];
#pragma unroll
    for (int i = 0; i < 4; i++)
#pragma unroll
        for (int k = 0; k < 4; k++) acc[i][k] = 0.f;
#pragma unroll 4
    for (int j = 0; j < 64; j++) {
        float4 va = *reinterpret_cast<const float4*>(&sT[j * 68 + a]);
        float4 vb = *reinterpret_cast<const float4*>(&sT[j * 68 + b]);
        float av[4] = {va.x, va.y, va.z, va.w};
#pragma unroll
        for (int i = 0; i < 4; i++) {
            acc[i][0] += av[i] * vb.x; acc[i][1] += av[i] * vb.y;
            acc[i][2] += av[i] * vb.z; acc[i][3] += av[i] * vb.w;
        }
    }
#pragma unroll
    for (int i = 0; i < 4; i++)
#pragma unroll
        for (int k = 0; k < 4; k++)
            atomicAdd(&g_G2[(a + i) * S2 + b + k], acc[i][k]);
}

// -------- C = A @ V2^T via tf32 mma (+ fused sumsq(A)) ----------------------
// grid (32, 8): 128-row i tiles, 8 splits over j. Each split writes its own
// partial buffer g_Cp[split] with plain stores (no atomics).
__global__ __launch_bounds__(256) void k_across(const float* __restrict__ A,
                                                const float* __restrict__ V2) {
    __shared__ unsigned sA[128 * RPAD];
    __shared__ unsigned sV[S2 * RPAD];
    int t = threadIdx.x;
    int lane = t & 31, warp = t >> 5;
    int wi = warp >> 1, ws = warp & 1;          // 4 x 2 warp grid
    int g = lane >> 2, q4 = lane & 3;
    int i0 = blockIdx.x * 128;
    int jbeg = blockIdx.y * (N / 8);
    int jend = jbeg + (N / 8);

    float acc[2][4][4];
#pragma unroll
    for (int m = 0; m < 2; m++)
#pragma unroll
        for (int n = 0; n < 4; n++)
#pragma unroll
            for (int q = 0; q < 4; q++) acc[m][n][q] = 0.f;
    float ssq = 0.f;

    int lrow = t >> 1, lhalf = t & 1;
    for (int j0 = jbeg; j0 < jend; j0 += 32) {
#pragma unroll
        for (int q = 0; q < 4; q++) {
            int c = lhalf * 16 + q * 4;
            float4 v = *reinterpret_cast<const float4*>(A + (i0 + lrow) * N + j0 + c);
            ssq += v.x * v.x + v.y * v.y + v.z * v.z + v.w * v.w;
            sA[lrow * RPAD + c + 0] = f2tf32(v.x);
            sA[lrow * RPAD + c + 1] = f2tf32(v.y);
            sA[lrow * RPAD + c + 2] = f2tf32(v.z);
            sA[lrow * RPAD + c + 3] = f2tf32(v.w);
        }
#pragma unroll
        for (int q = 0; q < 2; q++) {
            int e = t * 2 + q;
            int r = e >> 3, c = (e & 7) * 4;
            float4 v = *reinterpret_cast<const float4*>(V2 + r * N + j0 + c);
            sV[r * RPAD + c + 0] = f2tf32(v.x);
            sV[r * RPAD + c + 1] = f2tf32(v.y);
            sV[r * RPAD + c + 2] = f2tf32(v.z);
            sV[r * RPAD + c + 3] = f2tf32(v.w);
        }
        __syncthreads();
#pragma unroll
        for (int ks = 0; ks < 4; ks++) {
            int kk = ks * 8;
            unsigned a[2][4], b[4][2];
#pragma unroll
            for (int m = 0; m < 2; m++) {
                int r = wi * 32 + m * 16;
                a[m][0] = sA[(r + g) * RPAD + kk + q4];
                a[m][1] = sA[(r + g + 8) * RPAD + kk + q4];
                a[m][2] = sA[(r + g) * RPAD + kk + q4 + 4];
                a[m][3] = sA[(r + g + 8) * RPAD + kk + q4 + 4];
            }
#pragma unroll
            for (int n = 0; n < 4; n++) {
                int c = ws * 32 + n * 8;
                b[n][0] = sV[(c + g) * RPAD + kk + q4];
                b[n][1] = sV[(c + g) * RPAD + kk + q4 + 4];
            }
#pragma unroll
            for (int m = 0; m < 2; m++)
#pragma unroll
                for (int n = 0; n < 4; n++)
                    mma_tf32(acc[m][n], a[m][0], a[m][1], a[m][2], a[m][3],
                             b[n][0], b[n][1]);
        }
        __syncthreads();
    }
    float* out = g_Cp[blockIdx.y];
#pragma unroll
    for (int m = 0; m < 2; m++) {
        int r0 = i0 + wi * 32 + m * 16 + g;
#pragma unroll
        for (int n = 0; n < 4; n++) {
            int c = ws * 32 + n * 8 + q4 * 2;
            *reinterpret_cast<float2*>(out + r0 * S2 + c)       = make_float2(acc[m][n][0], acc[m][n][1]);
            *reinterpret_cast<float2*>(out + (r0 + 8) * S2 + c) = make_float2(acc[m][n][2], acc[m][n][3]);
        }
    }
    float bs = blockReduceSum(ssq);
    if (t == 0) atomicAdd(&g_acc[0], (double)bs);
}

// ---------------- elementwise dot reductions --------------------------------
__global__ void k_dot(int mode) {
    int tid = blockIdx.x * blockDim.x + threadIdx.x;
    int stride = gridDim.x * blockDim.x;
    float s = 0.f;
    if (mode == 0) {
        for (int i = tid; i < S2 * S2; i += stride) s += g_G1[i] * g_G2[i];
    } else {
        for (int i = tid; i < N * S2; i += stride) {
            float c = 0.f;
#pragma unroll
            for (int p = 0; p < 8; p++) c += g_Cp[p][i];
            s += g_W2[i] * c;
        }
    }
    float bs = blockReduceSum(s);
    if (threadIdx.x == 0) atomicAdd(&g_acc[mode == 0 ? 2 : 1], (double)bs);
}

// -------- fused refl_sim tile via tf32 mma: 128x128 per block ---------------
__global__ __launch_bounds__(256) void k_refl(const float* __restrict__ sim) {
    __shared__ unsigned sI[128 * RPAD];
    __shared__ unsigned sJ[128 * RPAD];
    int t = threadIdx.x;
    int lane = t & 31, warp = t >> 5;
    int wi = warp >> 1, wj = warp & 1;          // 4 x 2 warp grid
    int g = lane >> 2, q4 = lane & 3;
    int i0 = blockIdx.y * 128, j0 = blockIdx.x * 128;

    float acc[2][8][4];
#pragma unroll
    for (int m = 0; m < 2; m++)
#pragma unroll
        for (int n = 0; n < 8; n++)
#pragma unroll
            for (int q = 0; q < 4; q++) acc[m][n][q] = 0.f;

    int lrow = t >> 1, lhalf = t & 1;
    for (int k0 = 0; k0 < S0; k0 += 32) {
#pragma unroll
        for (int q = 0; q < 4; q++) {
            int c = lhalf * 16 + q * 4;
            float4 v = *reinterpret_cast<const float4*>(g_hn + (i0 + lrow) * S0 + k0 + c);
            sI[lrow * RPAD + c + 0] = f2tf32(v.x);
            sI[lrow * RPAD + c + 1] = f2tf32(v.y);
            sI[lrow * RPAD + c + 2] = f2tf32(v.z);
            sI[lrow * RPAD + c + 3] = f2tf32(v.w);
            float4 w = *reinterpret_cast<const float4*>(g_hn + (j0 + lrow) * S0 + k0 + c);
            sJ[lrow * RPAD + c + 0] = f2tf32(w.x);
            sJ[lrow * RPAD + c + 1] = f2tf32(w.y);
            sJ[lrow * RPAD + c + 2] = f2tf32(w.z);
            sJ[lrow * RPAD + c + 3] = f2tf32(w.w);
        }
        __syncthreads();
#pragma unroll
        for (int ks = 0; ks < 4; ks++) {
            int kk = ks * 8;
            unsigned a[2][4], b[8][2];
#pragma unroll
            for (int m = 0; m < 2; m++) {
                int r = wi * 32 + m * 16;
                a[m][0] = sI[(r + g) * RPAD + kk + q4];
                a[m][1] = sI[(r + g + 8) * RPAD + kk + q4];
                a[m][2] = sI[(r + g) * RPAD + kk + q4 + 4];
                a[m][3] = sI[(r + g + 8) * RPAD + kk + q4 + 4];
            }
#pragma unroll
            for (int n = 0; n < 8; n++) {
                int c = wj * 64 + n * 8;
                b[n][0] = sJ[(c + g) * RPAD + kk + q4];
                b[n][1] = sJ[(c + g) * RPAD + kk + q4 + 4];
            }
#pragma unroll
            for (int m = 0; m < 2; m++)
#pragma unroll
                for (int n = 0; n < 8; n++)
                    mma_tf32(acc[m][n], a[m][0], a[m][1], a[m][2], a[m][3],
                             b[n][0], b[n][1]);
        }
        __syncthreads();
    }

#pragma unroll
    for (int m = 0; m < 2; m++) {
        float rs0 = 0.f, rs1 = 0.f, rp0 = 0.f, rp1 = 0.f;
        int r0 = i0 + wi * 32 + m * 16 + g;
#pragma unroll
        for (int n = 0; n < 8; n++) {
            int c = j0 + wj * 64 + n * 8 + q4 * 2;
            float2 s0 = *reinterpret_cast<const float2*>(sim + r0 * N + c);
            float2 s1 = *reinterpret_cast<const float2*>(sim + (r0 + 8) * N + c);
            float e0 = __expf(2.f * acc[m][n][0]);
            float e1 = __expf(2.f * acc[m][n][1]);
            float e2 = __expf(2.f * acc[m][n][2]);
            float e3 = __expf(2.f * acc[m][n][3]);
            rs0 += e0 + e1;
            rs1 += e2 + e3;
            rp0 += (s0.x > 0.9f ? e0 : 0.f) + (s0.y > 0.9f ? e1 : 0.f);
            rp1 += (s1.x > 0.9f ? e2 : 0.f) + (s1.y > 0.9f ? e3 : 0.f);
        }
        rs0 += __shfl_xor_sync(0xffffffffu, rs0, 1);
        rs0 += __shfl_xor_sync(0xffffffffu, rs0, 2);
        rs1 += __shfl_xor_sync(0xffffffffu, rs1, 1);
        rs1 += __shfl_xor_sync(0xffffffffu, rs1, 2);
        rp0 += __shfl_xor_sync(0xffffffffu, rp0, 1);
        rp0 += __shfl_xor_sync(0xffffffffu, rp0, 2);
        rp1 += __shfl_xor_sync(0xffffffffu, rp1, 1);
        rp1 += __shfl_xor_sync(0xffffffffu, rp1, 2);
        if (q4 == 0) {
            atomicAdd(&g_total [r0],     rs0);
            atomicAdd(&g_possim[r0],     rp0);
            atomicAdd(&g_total [r0 + 8], rs1);
            atomicAdd(&g_possim[r0 + 8], rp1);
        }
    }
}

// -------- clique / neighbor positive sums via gather (set-dedupe) ----------
__global__ void k_gather(const int* __restrict__ clq, const int* __restrict__ ngh) {
    int tid = blockIdx.x * blockDim.x + threadIdx.x;
    if (tid >= N * 24) return;
    int i = tid / 24, m = tid % 24;
    int j; float* out;
    if (m < 8) {
        j = clq[i * 8 + m];
        for (int p = 0; p < m; p++) if (clq[i * 8 + p] == j) return;  // set semantics
        out = g_posclq;
    } else {
        int mm = m - 8;
        j = ngh[i * 16 + mm];
        for (int p = 0; p < mm; p++) if (ngh[i * 16 + p] == j) return;
        out = g_posngh;
    }
    const float4* hi = reinterpret_cast<const float4*>(g_hn + i * S0);
    const float4* hj = reinterpret_cast<const float4*>(g_hn + j * S0);
    float d = 0.f;
#pragma unroll 8
    for (int s = 0; s < 64; s++) {
        float4 x = hi[s], y = hj[s];
        d += x.x * y.x + x.y * y.y + x.z * y.z + x.w * y.w;
    }
    atomicAdd(&out[i], expf(2.f * d));
}

// ---------------- loss5: sum min(X,0)^2 over all 4 factors ------------------
__global__ void k_loss5(const float* __restrict__ U0, const float* __restrict__ U1,
                        const float* __restrict__ U2, const float* __restrict__ V2) {
    int tid = blockIdx.x * blockDim.x + threadIdx.x;
    int stride = gridDim.x * blockDim.x;
    float s = 0.f;
    for (int i = tid; i < N * S0; i += stride) { float v = U0[i]; if (v < 0.f) s += v * v; }
    for (int i = tid; i < S0 * S1; i += stride) { float v = U1[i]; if (v < 0.f) s += v * v; }
    for (int i = tid; i < S1 * S2; i += stride) { float v = U2[i]; if (v < 0.f) s += v * v; }
    for (int i = tid; i < S2 * N; i += stride) { float v = V2[i]; if (v < 0.f) s += v * v; }
    float bs = blockReduceSum(s);
    if (threadIdx.x == 0) atomicAdd(&g_acc[3], (double)bs);
}

// ---------------- contrastive -log(pos/total) sums --------------------------
__global__ void k_contrast() {
    int tid = blockIdx.x * blockDim.x + threadIdx.x;
    int stride = gridDim.x * blockDim.x;
    float sc = 0.f, sn = 0.f, ssim = 0.f;
    for (int i = tid; i < N; i += stride) {
        float tot = g_total[i];
        float c1 = g_posclq[i] / tot;
        float c2 = g_posngh[i] / tot;
        float c3 = g_possim[i] / tot;
        if (c1 != 0.f) sc   -= logf(c1);
        if (c2 != 0.f) sn   -= logf(c2);
        if (c3 != 0.f) ssim -= logf(c3);
    }
    float b1 = blockReduceSum(sc);
    float b2 = blockReduceSum(sn);
    float b3 = blockReduceSum(ssim);
    if (threadIdx.x == 0) {
        atomicAdd(&g_acc[4], (double)b1);
        atomicAdd(&g_acc[5], (double)b2);
        atomicAdd(&g_acc[6], (double)b3);
    }
}

// ---------------- final combine ---------------------------------------------
__global__ void k_final(float* out) {
    double l1 = g_acc[0] - 2.0 * g_acc[1] + g_acc[2];
    double l2 = g_acc[4] / (double)N;
    double l3 = g_acc[5] / (double)N;
    double l4 = g_acc[6] / (double)N;
    double l5 = g_acc[3];
    double tot = l1 + 0.1 * l2 + 0.1 * l3 + 0.1 * l4 + l5;
    out[0] = (float)tot; out[1] = (float)l1; out[2] = (float)l2;
    out[3] = (float)l3;  out[4] = (float)l4; out[5] = (float)l5;
}

// ---------------- launch -----------------------------------------------------
extern "C" void kernel_launch(void* const* d_in, const int* in_sizes, int n_in,
                              void* d_out, int out_size) {
    const float* A    = (const float*)d_in[0];
    const float* U0   = (const float*)d_in[1];
    const float* U1   = (const float*)d_in[2];
    const float* U2   = (const float*)d_in[3];
    const float* V2   = (const float*)d_in[4];
    const float* fc1w = (const float*)d_in[5];
    const float* fc1b = (const float*)d_in[6];
    const float* fc2w = (const float*)d_in[7];
    const float* fc2b = (const float*)d_in[8];
    const float* sim  = (const float*)d_in[9];
    const int*   clq  = (const int*)d_in[10];
    const int*   ngh  = (const int*)d_in[11];
    float* out = (float*)d_out;

    static bool attr_done = false;
    if (!attr_done) {
        cudaFuncSetAttribute(k_proj, cudaFuncAttributeMaxDynamicSharedMemorySize,
                             PROJ_SMEM_FLOATS * 4);
        attr_done = true;
    }

    k_zero<<<256, 256>>>();
    k_factor<<<N / 16, 256>>>(U0, U1, U2);
    k_proj<<<N / 32, 256, PROJ_SMEM_FLOATS * 4>>>(V2, fc1w, fc1b, fc2w, fc2b);
    k_gram1<<<64, 256>>>();
    k_gram2<<<64, 256>>>(V2);
    k_across<<<dim3(32, 8), 256>>>(A, V2);
    k_dot<<<64, 256>>>(0);
    k_dot<<<64, 256>>>(1);
    k_refl<<<dim3(32, 32), 256>>>(sim);
    k_gather<<<(N * 24 + 255) / 256, 256>>>(clq, ngh);
    k_loss5<<<128, 256>>>(U0, U1, U2, V2);
    k_contrast<<<32, 256>>>();
    k_final<<<1, 1>>>(out);
}

// round 8
// speedup vs baseline: 5.2830x; 1.1150x over previous
#include <cuda_runtime.h>
#include <math.h>

#define N   4096
#define S0  256
#define S1  128
#define S2  64
#define RPAD 36

// ---------------- scratch (device globals; no allocations allowed) ----------
__device__ __align__(16) float g_W2[N * S2];     // (U0@U1)@U2            [N,64]
__device__ __align__(16) float g_Cp[8][N * S2];  // A @ V2^T partials     [N,64]
__device__ __align__(16) float g_hn[N * S0];     // row-normalized h      [N,256]
__device__ float g_G1[S2 * S2];                  // W2^T W2
__device__ float g_G2[S2 * S2];                  // V2 V2^T
__device__ float g_total [N];
__device__ float g_possim[N];
__device__ float g_posclq[N];
__device__ float g_posngh[N];
// 0: sumsq(A)  1: <W2, A V2^T>  2: <G1,G2>  3: loss5
// 4: clique -log sum  5: neighbor -log sum  6: sim -log sum
__device__ double g_acc[8];

// ---------------- helpers ---------------------------------------------------
__device__ __forceinline__ float blockReduceSum(float v) {
    __shared__ float sh[33];
    int lane = threadIdx.x & 31, w = threadIdx.x >> 5;
#pragma unroll
    for (int o = 16; o; o >>= 1) v += __shfl_down_sync(0xffffffffu, v, o);
    if (lane == 0) sh[w] = v;
    __syncthreads();
    if (threadIdx.x == 0) {
        int nw = (blockDim.x + 31) >> 5;
        float r = 0.f;
        for (int x = 0; x < nw; x++) r += sh[x];
        sh[32] = r;
    }
    __syncthreads();
    float r = sh[32];
    __syncthreads();
    return r;
}

__device__ __forceinline__ unsigned f2tf32(float x) {
    unsigned r;
    asm("cvt.rna.tf32.f32 %0, %1;" : "=r"(r) : "f"(x));
    return r;
}

__device__ __forceinline__ void mma_tf32(float* c,
                                         unsigned a0, unsigned a1, unsigned a2, unsigned a3,
                                         unsigned b0, unsigned b1) {
    asm volatile(
        "mma.sync.aligned.m16n8k8.row.col.f32.tf32.tf32.f32 "
        "{%0,%1,%2,%3},{%4,%5,%6,%7},{%8,%9},{%0,%1,%2,%3};"
        : "+f"(c[0]), "+f"(c[1]), "+f"(c[2]), "+f"(c[3])
        : "r"(a0), "r"(a1), "r"(a2), "r"(a3), "r"(b0), "r"(b1));
}

// ---------------- zero scratch ----------------------------------------------
__global__ void k_zero() {
    int tid = blockIdx.x * blockDim.x + threadIdx.x;
    int stride = gridDim.x * blockDim.x;
    for (int i = tid; i < S2 * S2; i += stride) { g_G1[i] = 0.f; g_G2[i] = 0.f; }
    for (int i = tid; i < N; i += stride) {
        g_total[i] = 0.f; g_possim[i] = 0.f; g_posclq[i] = 0.f; g_posngh[i] = 0.f;
    }
    if (tid < 8) g_acc[tid] = 0.0;
}

// =================== fused layer A: factor (256 blocks) + proj (128) ========
// dynamic smem arena: 21120 floats (84480 B)
#define PROJ_SMEM_FLOATS 21120

__device__ __forceinline__ void body_factor(const float* __restrict__ U0,
                                            const float* __restrict__ U1,
                                            const float* __restrict__ U2,
                                            float* dsm, int bx) {
    float* sU0 = dsm;            // [16][256]
    float* sU1 = dsm + 4096;     // [32][132]
    float* sW1 = dsm + 8320;     // [16][132]
    int t = threadIdx.x;
    int i0 = bx * 16;
#pragma unroll
    for (int q = 0; q < 16; q++) {
        int e = t + q * 256;
        int r = e >> 8, k = e & 255;
        sU0[r * 256 + k] = U0[(i0 + r) * S0 + k];
    }
    int ty = t >> 5, tx = t & 31;
    float accw[2][4];
#pragma unroll
    for (int i = 0; i < 2; i++)
#pragma unroll
        for (int k = 0; k < 4; k++) accw[i][k] = 0.f;
    for (int k0 = 0; k0 < S0; k0 += 32) {
        __syncthreads();
#pragma unroll
        for (int q = 0; q < 16; q++) {
            int e = t + q * 256;
            int kk = e >> 7, j = e & 127;
            sU1[kk * 132 + j] = U1[(k0 + kk) * S1 + j];
        }
        __syncthreads();
#pragma unroll
        for (int kk = 0; kk < 32; kk++) {
            float4 b = *reinterpret_cast<const float4*>(&sU1[kk * 132 + tx * 4]);
            float a0 = sU0[(ty * 2 + 0) * 256 + k0 + kk];
            float a1 = sU0[(ty * 2 + 1) * 256 + k0 + kk];
            accw[0][0] += a0 * b.x; accw[0][1] += a0 * b.y;
            accw[0][2] += a0 * b.z; accw[0][3] += a0 * b.w;
            accw[1][0] += a1 * b.x; accw[1][1] += a1 * b.y;
            accw[1][2] += a1 * b.z; accw[1][3] += a1 * b.w;
        }
    }
    __syncthreads();
#pragma unroll
    for (int i = 0; i < 2; i++)
        *reinterpret_cast<float4*>(&sW1[(ty * 2 + i) * 132 + tx * 4]) =
            make_float4(accw[i][0], accw[i][1], accw[i][2], accw[i][3]);
    __syncthreads();
    int tn = t >> 4, tc = t & 15;
    float acc2[4] = {0.f, 0.f, 0.f, 0.f};
#pragma unroll 4
    for (int k = 0; k < S1; k++) {
        float a = sW1[tn * 132 + k];
        float4 b = *reinterpret_cast<const float4*>(&U2[k * S2 + tc * 4]);
        acc2[0] += a * b.x; acc2[1] += a * b.y;
        acc2[2] += a * b.z; acc2[3] += a * b.w;
    }
    *reinterpret_cast<float4*>(&g_W2[(i0 + tn) * S2 + tc * 4]) =
        make_float4(acc2[0], acc2[1], acc2[2], acc2[3]);
}

__device__ __forceinline__ void body_proj(const float* __restrict__ V2,
                                          const float* __restrict__ fc1w,
                                          const float* __restrict__ fc1b,
                                          const float* __restrict__ fc2w,
                                          const float* __restrict__ fc2b,
                                          float* dsm, int bx) {
    float* sXT  = dsm;           // [64][40]
    float* sW1T = dsm + 2560;    // [64][132]
    float* sW2T = dsm;           // [128][132] (stage 2, aliases stage-1 arrays)
    float* sH1  = dsm + 16896;   // [32][132]
    int t = threadIdx.x;
    int n0 = bx * 32;
    int ty = t >> 5, tx = t & 31;

#pragma unroll
    for (int q = 0; q < 8; q++) {
        int e = t + q * 256;
        int s = e >> 5, n = e & 31;
        sXT[s * 40 + n] = V2[s * N + n0 + n];
    }
#pragma unroll
    for (int q = 0; q < 32; q++) {
        int e = t + q * 256;
        int j = e >> 6, s = e & 63;
        sW1T[s * 132 + j] = fc1w[e];
    }
    __syncthreads();

    float4 b1v = *reinterpret_cast<const float4*>(&fc1b[tx * 4]);
    float acc1[4][4];
#pragma unroll
    for (int i = 0; i < 4; i++) {
        acc1[i][0] = b1v.x; acc1[i][1] = b1v.y;
        acc1[i][2] = b1v.z; acc1[i][3] = b1v.w;
    }
#pragma unroll 4
    for (int s = 0; s < S2; s++) {
        float4 a = *reinterpret_cast<const float4*>(&sXT[s * 40 + ty * 4]);
        float4 b = *reinterpret_cast<const float4*>(&sW1T[s * 132 + tx * 4]);
        float av[4] = {a.x, a.y, a.z, a.w};
#pragma unroll
        for (int i = 0; i < 4; i++) {
            acc1[i][0] += av[i] * b.x; acc1[i][1] += av[i] * b.y;
            acc1[i][2] += av[i] * b.z; acc1[i][3] += av[i] * b.w;
        }
    }
#pragma unroll
    for (int i = 0; i < 4; i++) {
        float4 h;
        h.x = acc1[i][0] > 0.f ? acc1[i][0] : expm1f(acc1[i][0]);
        h.y = acc1[i][1] > 0.f ? acc1[i][1] : expm1f(acc1[i][1]);
        h.z = acc1[i][2] > 0.f ? acc1[i][2] : expm1f(acc1[i][2]);
        h.w = acc1[i][3] > 0.f ? acc1[i][3] : expm1f(acc1[i][3]);
        *reinterpret_cast<float4*>(&sH1[(ty * 4 + i) * 132 + tx * 4]) = h;
    }

    float h[2][4][4];
#pragma unroll
    for (int c = 0; c < 2; c++) {
        __syncthreads();
#pragma unroll
        for (int q = 0; q < 64; q++) {
            int e = t + q * 256;
            int lt = e >> 7, j = e & 127;
            sW2T[j * 132 + lt] = fc2w[(c * 128 + lt) * S1 + j];
        }
        __syncthreads();
        float4 b2v = *reinterpret_cast<const float4*>(&fc2b[c * 128 + tx * 4]);
#pragma unroll
        for (int i = 0; i < 4; i++) {
            h[c][i][0] = b2v.x; h[c][i][1] = b2v.y;
            h[c][i][2] = b2v.z; h[c][i][3] = b2v.w;
        }
#pragma unroll 4
        for (int j = 0; j < S1; j++) {
            float4 b = *reinterpret_cast<const float4*>(&sW2T[j * 132 + tx * 4]);
#pragma unroll
            for (int i = 0; i < 4; i++) {
                float a = sH1[(ty * 4 + i) * 132 + j];
                h[c][i][0] += a * b.x; h[c][i][1] += a * b.y;
                h[c][i][2] += a * b.z; h[c][i][3] += a * b.w;
            }
        }
    }
#pragma unroll
    for (int i = 0; i < 4; i++) {
        float ss = 0.f;
#pragma unroll
        for (int c = 0; c < 2; c++)
#pragma unroll
            for (int k = 0; k < 4; k++) ss += h[c][i][k] * h[c][i][k];
#pragma unroll
        for (int o = 16; o; o >>= 1) ss += __shfl_xor_sync(0xffffffffu, ss, o);
        float inv = 1.f / fmaxf(sqrtf(ss), 1e-12f);
        int row = n0 + ty * 4 + i;
#pragma unroll
        for (int c = 0; c < 2; c++)
            *reinterpret_cast<float4*>(&g_hn[row * S0 + c * 128 + tx * 4]) =
                make_float4(h[c][i][0] * inv, h[c][i][1] * inv,
                            h[c][i][2] * inv, h[c][i][3] * inv);
    }
}

__global__ __launch_bounds__(256) void k_fused_a(
    const float* __restrict__ U0, const float* __restrict__ U1,
    const float* __restrict__ U2, const float* __restrict__ V2,
    const float* __restrict__ fc1w, const float* __restrict__ fc1b,
    const float* __restrict__ fc2w, const float* __restrict__ fc2b) {
    extern __shared__ float dsm[];
    int b = blockIdx.x;
    if (b < 256) body_factor(U0, U1, U2, dsm, b);
    else         body_proj(V2, fc1w, fc1b, fc2w, fc2b, dsm, b - 256);
}

// =================== fused layer B bodies ===================================

__device__ __forceinline__ void body_across(const float* __restrict__ A,
                                            const float* __restrict__ V2,
                                            unsigned* dsmu, int bx, int by) {
    unsigned* sA = dsmu;                 // [128][RPAD]
    unsigned* sV = dsmu + 128 * RPAD;    // [64][RPAD]
    int t = threadIdx.x;
    int lane = t & 31, warp = t >> 5;
    int wi = warp >> 1, ws = warp & 1;
    int g = lane >> 2, q4 = lane & 3;
    int i0 = bx * 128;
    int jbeg = by * (N / 8);
    int jend = jbeg + (N / 8);

    float acc[2][4][4];
#pragma unroll
    for (int m = 0; m < 2; m++)
#pragma unroll
        for (int n = 0; n < 4; n++)
#pragma unroll
            for (int q = 0; q < 4; q++) acc[m][n][q] = 0.f;
    float ssq = 0.f;

    int lrow = t >> 1, lhalf = t & 1;
    for (int j0 = jbeg; j0 < jend; j0 += 32) {
#pragma unroll
        for (int q = 0; q < 4; q++) {
            int c = lhalf * 16 + q * 4;
            float4 v = *reinterpret_cast<const float4*>(A + (i0 + lrow) * N + j0 + c);
            ssq += v.x * v.x + v.y * v.y + v.z * v.z + v.w * v.w;
            sA[lrow * RPAD + c + 0] = f2tf32(v.x);
            sA[lrow * RPAD + c + 1] = f2tf32(v.y);
            sA[lrow * RPAD + c + 2] = f2tf32(v.z);
            sA[lrow * RPAD + c + 3] = f2tf32(v.w);
        }
#pragma unroll
        for (int q = 0; q < 2; q++) {
            int e = t * 2 + q;
            int r = e >> 3, c = (e & 7) * 4;
            float4 v = *reinterpret_cast<const float4*>(V2 + r * N + j0 + c);
            sV[r * RPAD + c + 0] = f2tf32(v.x);
            sV[r * RPAD + c + 1] = f2tf32(v.y);
            sV[r * RPAD + c + 2] = f2tf32(v.z);
            sV[r * RPAD + c + 3] = f2tf32(v.w);
        }
        __syncthreads();
#pragma unroll
        for (int ks = 0; ks < 4; ks++) {
            int kk = ks * 8;
            unsigned a[2][4], b[4][2];
#pragma unroll
            for (int m = 0; m < 2; m++) {
                int r = wi * 32 + m * 16;
                a[m][0] = sA[(r + g) * RPAD + kk + q4];
                a[m][1] = sA[(r + g + 8) * RPAD + kk + q4];
                a[m][2] = sA[(r + g) * RPAD + kk + q4 + 4];
                a[m][3] = sA[(r + g + 8) * RPAD + kk + q4 + 4];
            }
#pragma unroll
            for (int n = 0; n < 4; n++) {
                int c = ws * 32 + n * 8;
                b[n][0] = sV[(c + g) * RPAD + kk + q4];
                b[n][1] = sV[(c + g) * RPAD + kk + q4 + 4];
            }
#pragma unroll
            for (int m = 0; m < 2; m++)
#pragma unroll
                for (int n = 0; n < 4; n++)
                    mma_tf32(acc[m][n], a[m][0], a[m][1], a[m][2], a[m][3],
                             b[n][0], b[n][1]);
        }
        __syncthreads();
    }
    float* out = g_Cp[by];
#pragma unroll
    for (int m = 0; m < 2; m++) {
        int r0 = i0 + wi * 32 + m * 16 + g;
#pragma unroll
        for (int n = 0; n < 4; n++) {
            int c = ws * 32 + n * 8 + q4 * 2;
            *reinterpret_cast<float2*>(out + r0 * S2 + c)       = make_float2(acc[m][n][0], acc[m][n][1]);
            *reinterpret_cast<float2*>(out + (r0 + 8) * S2 + c) = make_float2(acc[m][n][2], acc[m][n][3]);
        }
    }
    float bs = blockReduceSum(ssq);
    if (t == 0) atomicAdd(&g_acc[0], (double)bs);
}

__device__ __forceinline__ void body_refl(const float* __restrict__ sim,
                                          unsigned* dsmu, int bx, int by) {
    unsigned* sI = dsmu;                 // [128][RPAD]
    unsigned* sJ = dsmu + 128 * RPAD;    // [128][RPAD]
    int t = threadIdx.x;
    int lane = t & 31, warp = t >> 5;
    int wi = warp >> 1, wj = warp & 1;
    int g = lane >> 2, q4 = lane & 3;
    int i0 = by * 128, j0 = bx * 128;

    float acc[2][8][4];
#pragma unroll
    for (int m = 0; m < 2; m++)
#pragma unroll
        for (int n = 0; n < 8; n++)
#pragma unroll
            for (int q = 0; q < 4; q++) acc[m][n][q] = 0.f;

    int lrow = t >> 1, lhalf = t & 1;
    for (int k0 = 0; k0 < S0; k0 += 32) {
#pragma unroll
        for (int q = 0; q < 4; q++) {
            int c = lhalf * 16 + q * 4;
            float4 v = *reinterpret_cast<const float4*>(g_hn + (i0 + lrow) * S0 + k0 + c);
            sI[lrow * RPAD + c + 0] = f2tf32(v.x);
            sI[lrow * RPAD + c + 1] = f2tf32(v.y);
            sI[lrow * RPAD + c + 2] = f2tf32(v.z);
            sI[lrow * RPAD + c + 3] = f2tf32(v.w);
            float4 w = *reinterpret_cast<const float4*>(g_hn + (j0 + lrow) * S0 + k0 + c);
            sJ[lrow * RPAD + c + 0] = f2tf32(w.x);
            sJ[lrow * RPAD + c + 1] = f2tf32(w.y);
            sJ[lrow * RPAD + c + 2] = f2tf32(w.z);
            sJ[lrow * RPAD + c + 3] = f2tf32(w.w);
        }
        __syncthreads();
#pragma unroll
        for (int ks = 0; ks < 4; ks++) {
            int kk = ks * 8;
            unsigned a[2][4], b[8][2];
#pragma unroll
            for (int m = 0; m < 2; m++) {
                int r = wi * 32 + m * 16;
                a[m][0] = sI[(r + g) * RPAD + kk + q4];
                a[m][1] = sI[(r + g + 8) * RPAD + kk + q4];
                a[m][2] = sI[(r + g) * RPAD + kk + q4 + 4];
                a[m][3] = sI[(r + g + 8) * RPAD + kk + q4 + 4];
            }
#pragma unroll
            for (int n = 0; n < 8; n++) {
                int c = wj * 64 + n * 8;
                b[n][0] = sJ[(c + g) * RPAD + kk + q4];
                b[n][1] = sJ[(c + g) * RPAD + kk + q4 + 4];
            }
#pragma unroll
            for (int m = 0; m < 2; m++)
#pragma unroll
                for (int n = 0; n < 8; n++)
                    mma_tf32(acc[m][n], a[m][0], a[m][1], a[m][2], a[m][3],
                             b[n][0], b[n][1]);
        }
        __syncthreads();
    }

#pragma unroll
    for (int m = 0; m < 2; m++) {
        float rs0 = 0.f, rs1 = 0.f, rp0 = 0.f, rp1 = 0.f;
        int r0 = i0 + wi * 32 + m * 16 + g;
#pragma unroll
        for (int n = 0; n < 8; n++) {
            int c = j0 + wj * 64 + n * 8 + q4 * 2;
            float2 s0 = *reinterpret_cast<const float2*>(sim + r0 * N + c);
            float2 s1 = *reinterpret_cast<const float2*>(sim + (r0 + 8) * N + c);
            float e0 = __expf(2.f * acc[m][n][0]);
            float e1 = __expf(2.f * acc[m][n][1]);
            float e2 = __expf(2.f * acc[m][n][2]);
            float e3 = __expf(2.f * acc[m][n][3]);
            rs0 += e0 + e1;
            rs1 += e2 + e3;
            rp0 += (s0.x > 0.9f ? e0 : 0.f) + (s0.y > 0.9f ? e1 : 0.f);
            rp1 += (s1.x > 0.9f ? e2 : 0.f) + (s1.y > 0.9f ? e3 : 0.f);
        }
        rs0 += __shfl_xor_sync(0xffffffffu, rs0, 1);
        rs0 += __shfl_xor_sync(0xffffffffu, rs0, 2);
        rs1 += __shfl_xor_sync(0xffffffffu, rs1, 1);
        rs1 += __shfl_xor_sync(0xffffffffu, rs1, 2);
        rp0 += __shfl_xor_sync(0xffffffffu, rp0, 1);
        rp0 += __shfl_xor_sync(0xffffffffu, rp0, 2);
        rp1 += __shfl_xor_sync(0xffffffffu, rp1, 1);
        rp1 += __shfl_xor_sync(0xffffffffu, rp1, 2);
        if (q4 == 0) {
            atomicAdd(&g_total [r0],     rs0);
            atomicAdd(&g_possim[r0],     rp0);
            atomicAdd(&g_total [r0 + 8], rs1);
            atomicAdd(&g_possim[r0 + 8], rp1);
        }
    }
}

__device__ __forceinline__ void body_gram1(float* sT, int bx) {
    int t = threadIdx.x;
    int k0 = bx * 32;
#pragma unroll
    for (int q = 0; q < 8; q++) {
        int e = t + q * 256;
        int r = e >> 6, c = e & 63;
        sT[r * 68 + c] = g_W2[(k0 + r) * S2 + c];
    }
    __syncthreads();
    int a = (t >> 4) * 4, b = (t & 15) * 4;
    float acc[4][4];
#pragma unroll
    for (int i = 0; i < 4; i++)
#pragma unroll
        for (int k = 0; k < 4; k++) acc[i][k] = 0.f;
#pragma unroll 4
    for (int r = 0; r < 32; r++) {
        float4 va = *reinterpret_cast<const float4*>(&sT[r * 68 + a]);
        float4 vb = *reinterpret_cast<const float4*>(&sT[r * 68 + b]);
        float av[4] = {va.x, va.y, va.z, va.w};
#pragma unroll
        for (int i = 0; i < 4; i++) {
            acc[i][0] += av[i] * vb.x; acc[i][1] += av[i] * vb.y;
            acc[i][2] += av[i] * vb.z; acc[i][3] += av[i] * vb.w;
        }
    }
#pragma unroll
    for (int i = 0; i < 4; i++)
#pragma unroll
        for (int k = 0; k < 4; k++)
            atomicAdd(&g_G1[(a + i) * S2 + b + k], acc[i][k]);
}

__device__ __forceinline__ void body_gram2(const float* __restrict__ V2,
                                           float* sT, int bx) {
    int t = threadIdx.x;
    int j0 = bx * 32;
#pragma unroll
    for (int q = 0; q < 8; q++) {
        int e = t + q * 256;
        int s = e >> 5, j = e & 31;
        sT[j * 68 + s] = V2[s * N + j0 + j];
    }
    __syncthreads();
    int a = (t >> 4) * 4, b = (t & 15) * 4;
    float acc[4][4];
#pragma unroll
    for (int i = 0; i < 4; i++)
#pragma unroll
        for (int k = 0; k < 4; k++) acc[i][k] = 0.f;
#pragma unroll 4
    for (int j = 0; j < 32; j++) {
        float4 va = *reinterpret_cast<const float4*>(&sT[j * 68 + a]);
        float4 vb = *reinterpret_cast<const float4*>(&sT[j * 68 + b]);
        float av[4] = {va.x, va.y, va.z, va.w};
#pragma unroll
        for (int i = 0; i < 4; i++) {
            acc[i][0] += av[i] * vb.x; acc[i][1] += av[i] * vb.y;
            acc[i][2] += av[i] * vb.z; acc[i][3] += av[i] * vb.w;
        }
    }
#pragma unroll
    for (int i = 0; i < 4; i++)
#pragma unroll
        for (int k = 0; k < 4; k++)
            atomicAdd(&g_G2[(a + i) * S2 + b + k], acc[i][k]);
}

__device__ __forceinline__ void body_loss5(const float* __restrict__ U0,
                                           const float* __restrict__ U1,
                                           const float* __restrict__ U2,
                                           const float* __restrict__ V2, int bx) {
    int tid = bx * 256 + threadIdx.x;
    int stride = 128 * 256;
    float s = 0.f;
    for (int i = tid; i < N * S0; i += stride) { float v = U0[i]; if (v < 0.f) s += v * v; }
    for (int i = tid; i < S0 * S1; i += stride) { float v = U1[i]; if (v < 0.f) s += v * v; }
    for (int i = tid; i < S1 * S2; i += stride) { float v = U2[i]; if (v < 0.f) s += v * v; }
    for (int i = tid; i < S2 * N; i += stride) { float v = V2[i]; if (v < 0.f) s += v * v; }
    float bs = blockReduceSum(s);
    if (threadIdx.x == 0) atomicAdd(&g_acc[3], (double)bs);
}

__device__ __forceinline__ void body_gather(const int* __restrict__ clq,
                                            const int* __restrict__ ngh, int bx) {
    int tid = bx * 256 + threadIdx.x;
    if (tid >= N * 24) return;
    int i = tid / 24, m = tid % 24;
    int j; float* out;
    if (m < 8) {
        j = clq[i * 8 + m];
        for (int p = 0; p < m; p++) if (clq[i * 8 + p] == j) return;  // set semantics
        out = g_posclq;
    } else {
        int mm = m - 8;
        j = ngh[i * 16 + mm];
        for (int p = 0; p < mm; p++) if (ngh[i * 16 + p] == j) return;
        out = g_posngh;
    }
    const float4* hi = reinterpret_cast<const float4*>(g_hn + i * S0);
    const float4* hj = reinterpret_cast<const float4*>(g_hn + j * S0);
    float d = 0.f;
#pragma unroll 8
    for (int s = 0; s < 64; s++) {
        float4 x = hi[s], y = hj[s];
        d += x.x * y.x + x.y * y.y + x.z * y.z + x.w * y.w;
    }
    atomicAdd(&out[i], expf(2.f * d));
}

// fused layer B: across[0,256) refl[256,1280) gram1[1280,1408)
//                gram2[1408,1536) loss5[1536,1664) gather[1664,2048)
__global__ __launch_bounds__(256) void k_fused_b(
    const float* __restrict__ A, const float* __restrict__ V2,
    const float* __restrict__ sim,
    const int* __restrict__ clq, const int* __restrict__ ngh,
    const float* __restrict__ U0, const float* __restrict__ U1,
    const float* __restrict__ U2) {
    extern __shared__ unsigned dsmu[];
    int b = blockIdx.x;
    if (b < 256) {
        body_across(A, V2, dsmu, b & 31, b >> 5);
    } else if (b < 1280) {
        int b2 = b - 256;
        body_refl(sim, dsmu, b2 & 31, b2 >> 5);
    } else if (b < 1408) {
        body_gram1(reinterpret_cast<float*>(dsmu), b - 1280);
    } else if (b < 1536) {
        body_gram2(V2, reinterpret_cast<float*>(dsmu), b - 1408);
    } else if (b < 1664) {
        body_loss5(U0, U1, U2, V2, b - 1536);
    } else {
        body_gather(clq, ngh, b - 1664);
    }
}

// =================== fused layer C: dots (64 blocks) + contrast (32) ========
__global__ __launch_bounds__(256) void k_fused_c() {
    int b = blockIdx.x;
    if (b < 64) {
        int tid = b * 256 + threadIdx.x;
        int stride = 64 * 256;
        float s2 = 0.f, s1 = 0.f;
        for (int i = tid; i < S2 * S2; i += stride) s2 += g_G1[i] * g_G2[i];
        for (int i = tid; i < N * S2; i += stride) {
            float c = 0.f;
#pragma unroll
            for (int p = 0; p < 8; p++) c += g_Cp[p][i];
            s1 += g_W2[i] * c;
        }
        float b2 = blockReduceSum(s2);
        float b1 = blockReduceSum(s1);
        if (threadIdx.x == 0) {
            atomicAdd(&g_acc[2], (double)b2);
            atomicAdd(&g_acc[1], (double)b1);
        }
    } else {
        int tid = (b - 64) * 256 + threadIdx.x;
        int stride = 32 * 256;
        float sc = 0.f, sn = 0.f, ssim = 0.f;
        for (int i = tid; i < N; i += stride) {
            float tot = g_total[i];
            float c1 = g_posclq[i] / tot;
            float c2 = g_posngh[i] / tot;
            float c3 = g_possim[i] / tot;
            if (c1 != 0.f) sc   -= logf(c1);
            if (c2 != 0.f) sn   -= logf(c2);
            if (c3 != 0.f) ssim -= logf(c3);
        }
        float b1 = blockReduceSum(sc);
        float b2 = blockReduceSum(sn);
        float b3 = blockReduceSum(ssim);
        if (threadIdx.x == 0) {
            atomicAdd(&g_acc[4], (double)b1);
            atomicAdd(&g_acc[5], (double)b2);
            atomicAdd(&g_acc[6], (double)b3);
        }
    }
}

// ---------------- final combine ---------------------------------------------
__global__ void k_final(float* out) {
    double l1 = g_acc[0] - 2.0 * g_acc[1] + g_acc[2];
    double l2 = g_acc[4] / (double)N;
    double l3 = g_acc[5] / (double)N;
    double l4 = g_acc[6] / (double)N;
    double l5 = g_acc[3];
    double tot = l1 + 0.1 * l2 + 0.1 * l3 + 0.1 * l4 + l5;
    out[0] = (float)tot; out[1] = (float)l1; out[2] = (float)l2;
    out[3] = (float)l3;  out[4] = (float)l4; out[5] = (float)l5;
}

// ---------------- launch -----------------------------------------------------
extern "C" void kernel_launch(void* const* d_in, const int* in_sizes, int n_in,
                              void* d_out, int out_size) {
    const float* A    = (const float*)d_in[0];
    const float* U0   = (const float*)d_in[1];
    const float* U1   = (const float*)d_in[2];
    const float* U2   = (const float*)d_in[3];
    const float* V2   = (const float*)d_in[4];
    const float* fc1w = (const float*)d_in[5];
    const float* fc1b = (const float*)d_in[6];
    const float* fc2w = (const float*)d_in[7];
    const float* fc2b = (const float*)d_in[8];
    const float* sim  = (const float*)d_in[9];
    const int*   clq  = (const int*)d_in[10];
    const int*   ngh  = (const int*)d_in[11];
    float* out = (float*)d_out;

    static bool attr_done = false;
    if (!attr_done) {
        cudaFuncSetAttribute(k_fused_a, cudaFuncAttributeMaxDynamicSharedMemorySize,
                             PROJ_SMEM_FLOATS * 4);
        attr_done = true;
    }

    k_zero<<<64, 256>>>();
    k_fused_a<<<384, 256, PROJ_SMEM_FLOATS * 4>>>(U0, U1, U2, V2,
                                                  fc1w, fc1b, fc2w, fc2b);
    k_fused_b<<<2048, 256, 2 * 128 * RPAD * 4>>>(A, V2, sim, clq, ngh, U0, U1, U2);
    k_fused_c<<<96, 256>>>();
    k_final<<<1, 1>>>(out);
}

// round 9
// speedup vs baseline: 6.2475x; 1.1826x over previous
#include <cuda_runtime.h>
#include <math.h>

#define N   4096
#define S0  256
#define S1  128
#define S2  64
#define RPAD 36

// ---------------- scratch (device globals; no allocations allowed) ----------
__device__ __align__(16) float g_W2[N * S2];     // (U0@U1)@U2            [N,64]
__device__ __align__(16) float g_hn[N * S0];     // row-normalized h      [N,256]
__device__ float g_G1[S2 * S2];                  // W2^T W2
__device__ float g_G2[S2 * S2];                  // V2 V2^T
__device__ float g_total [N];
__device__ float g_possim[N];
__device__ float g_posclq[N];
__device__ float g_posngh[N];
// 0: sumsq(A)  1: <W2, A V2^T>  2: <G1,G2>  3: loss5
// 4: clique -log sum  5: neighbor -log sum  6: sim -log sum
__device__ double g_acc[8];

// ---------------- helpers ---------------------------------------------------
__device__ __forceinline__ float blockReduceSum(float v) {
    __shared__ float sh[33];
    int lane = threadIdx.x & 31, w = threadIdx.x >> 5;
#pragma unroll
    for (int o = 16; o; o >>= 1) v += __shfl_down_sync(0xffffffffu, v, o);
    if (lane == 0) sh[w] = v;
    __syncthreads();
    if (threadIdx.x == 0) {
        int nw = (blockDim.x + 31) >> 5;
        float r = 0.f;
        for (int x = 0; x < nw; x++) r += sh[x];
        sh[32] = r;
    }
    __syncthreads();
    float r = sh[32];
    __syncthreads();
    return r;
}

__device__ __forceinline__ unsigned f2tf32(float x) {
    unsigned r;
    asm("cvt.rna.tf32.f32 %0, %1;" : "=r"(r) : "f"(x));
    return r;
}

__device__ __forceinline__ void mma_tf32(float* c,
                                         unsigned a0, unsigned a1, unsigned a2, unsigned a3,
                                         unsigned b0, unsigned b1) {
    asm volatile(
        "mma.sync.aligned.m16n8k8.row.col.f32.tf32.tf32.f32 "
        "{%0,%1,%2,%3},{%4,%5,%6,%7},{%8,%9},{%0,%1,%2,%3};"
        : "+f"(c[0]), "+f"(c[1]), "+f"(c[2]), "+f"(c[3])
        : "r"(a0), "r"(a1), "r"(a2), "r"(a3), "r"(b0), "r"(b1));
}

// ---------------- zero scratch ----------------------------------------------
__global__ void k_zero() {
    int tid = blockIdx.x * blockDim.x + threadIdx.x;
    int stride = gridDim.x * blockDim.x;
    for (int i = tid; i < S2 * S2; i += stride) { g_G1[i] = 0.f; g_G2[i] = 0.f; }
    for (int i = tid; i < N; i += stride) {
        g_total[i] = 0.f; g_possim[i] = 0.f; g_posclq[i] = 0.f; g_posngh[i] = 0.f;
    }
    if (tid < 8) g_acc[tid] = 0.0;
}

// =================== fused layer A: factor (256 blocks) + proj (128) ========
#define PROJ_SMEM_FLOATS 21120

__device__ __forceinline__ void body_factor(const float* __restrict__ U0,
                                            const float* __restrict__ U1,
                                            const float* __restrict__ U2,
                                            float* dsm, int bx) {
    float* sU0 = dsm;            // [16][256]
    float* sU1 = dsm + 4096;     // [32][132]
    float* sW1 = dsm + 8320;     // [16][132]
    int t = threadIdx.x;
    int i0 = bx * 16;
#pragma unroll
    for (int q = 0; q < 16; q++) {
        int e = t + q * 256;
        int r = e >> 8, k = e & 255;
        sU0[r * 256 + k] = U0[(i0 + r) * S0 + k];
    }
    int ty = t >> 5, tx = t & 31;
    float accw[2][4];
#pragma unroll
    for (int i = 0; i < 2; i++)
#pragma unroll
        for (int k = 0; k < 4; k++) accw[i][k] = 0.f;
    for (int k0 = 0; k0 < S0; k0 += 32) {
        __syncthreads();
#pragma unroll
        for (int q = 0; q < 16; q++) {
            int e = t + q * 256;
            int kk = e >> 7, j = e & 127;
            sU1[kk * 132 + j] = U1[(k0 + kk) * S1 + j];
        }
        __syncthreads();
#pragma unroll
        for (int kk = 0; kk < 32; kk++) {
            float4 b = *reinterpret_cast<const float4*>(&sU1[kk * 132 + tx * 4]);
            float a0 = sU0[(ty * 2 + 0) * 256 + k0 + kk];
            float a1 = sU0[(ty * 2 + 1) * 256 + k0 + kk];
            accw[0][0] += a0 * b.x; accw[0][1] += a0 * b.y;
            accw[0][2] += a0 * b.z; accw[0][3] += a0 * b.w;
            accw[1][0] += a1 * b.x; accw[1][1] += a1 * b.y;
            accw[1][2] += a1 * b.z; accw[1][3] += a1 * b.w;
        }
    }
    __syncthreads();
#pragma unroll
    for (int i = 0; i < 2; i++)
        *reinterpret_cast<float4*>(&sW1[(ty * 2 + i) * 132 + tx * 4]) =
            make_float4(accw[i][0], accw[i][1], accw[i][2], accw[i][3]);
    __syncthreads();
    int tn = t >> 4, tc = t & 15;
    float acc2[4] = {0.f, 0.f, 0.f, 0.f};
#pragma unroll 4
    for (int k = 0; k < S1; k++) {
        float a = sW1[tn * 132 + k];
        float4 b = *reinterpret_cast<const float4*>(&U2[k * S2 + tc * 4]);
        acc2[0] += a * b.x; acc2[1] += a * b.y;
        acc2[2] += a * b.z; acc2[3] += a * b.w;
    }
    *reinterpret_cast<float4*>(&g_W2[(i0 + tn) * S2 + tc * 4]) =
        make_float4(acc2[0], acc2[1], acc2[2], acc2[3]);
}

__device__ __forceinline__ void body_proj(const float* __restrict__ V2,
                                          const float* __restrict__ fc1w,
                                          const float* __restrict__ fc1b,
                                          const float* __restrict__ fc2w,
                                          const float* __restrict__ fc2b,
                                          float* dsm, int bx) {
    float* sXT  = dsm;           // [64][40]
    float* sW1T = dsm + 2560;    // [64][132]
    float* sW2T = dsm;           // [128][132] (stage 2, aliases stage-1 arrays)
    float* sH1  = dsm + 16896;   // [32][132]
    int t = threadIdx.x;
    int n0 = bx * 32;
    int ty = t >> 5, tx = t & 31;

#pragma unroll
    for (int q = 0; q < 8; q++) {
        int e = t + q * 256;
        int s = e >> 5, n = e & 31;
        sXT[s * 40 + n] = V2[s * N + n0 + n];
    }
#pragma unroll
    for (int q = 0; q < 32; q++) {
        int e = t + q * 256;
        int j = e >> 6, s = e & 63;
        sW1T[s * 132 + j] = fc1w[e];
    }
    __syncthreads();

    float4 b1v = *reinterpret_cast<const float4*>(&fc1b[tx * 4]);
    float acc1[4][4];
#pragma unroll
    for (int i = 0; i < 4; i++) {
        acc1[i][0] = b1v.x; acc1[i][1] = b1v.y;
        acc1[i][2] = b1v.z; acc1[i][3] = b1v.w;
    }
#pragma unroll 4
    for (int s = 0; s < S2; s++) {
        float4 a = *reinterpret_cast<const float4*>(&sXT[s * 40 + ty * 4]);
        float4 b = *reinterpret_cast<const float4*>(&sW1T[s * 132 + tx * 4]);
        float av[4] = {a.x, a.y, a.z, a.w};
#pragma unroll
        for (int i = 0; i < 4; i++) {
            acc1[i][0] += av[i] * b.x; acc1[i][1] += av[i] * b.y;
            acc1[i][2] += av[i] * b.z; acc1[i][3] += av[i] * b.w;
        }
    }
#pragma unroll
    for (int i = 0; i < 4; i++) {
        float4 h;
        h.x = acc1[i][0] > 0.f ? acc1[i][0] : expm1f(acc1[i][0]);
        h.y = acc1[i][1] > 0.f ? acc1[i][1] : expm1f(acc1[i][1]);
        h.z = acc1[i][2] > 0.f ? acc1[i][2] : expm1f(acc1[i][2]);
        h.w = acc1[i][3] > 0.f ? acc1[i][3] : expm1f(acc1[i][3]);
        *reinterpret_cast<float4*>(&sH1[(ty * 4 + i) * 132 + tx * 4]) = h;
    }

    float h[2][4][4];
#pragma unroll
    for (int c = 0; c < 2; c++) {
        __syncthreads();
#pragma unroll
        for (int q = 0; q < 64; q++) {
            int e = t + q * 256;
            int lt = e >> 7, j = e & 127;
            sW2T[j * 132 + lt] = fc2w[(c * 128 + lt) * S1 + j];
        }
        __syncthreads();
        float4 b2v = *reinterpret_cast<const float4*>(&fc2b[c * 128 + tx * 4]);
#pragma unroll
        for (int i = 0; i < 4; i++) {
            h[c][i][0] = b2v.x; h[c][i][1] = b2v.y;
            h[c][i][2] = b2v.z; h[c][i][3] = b2v.w;
        }
#pragma unroll 4
        for (int j = 0; j < S1; j++) {
            float4 b = *reinterpret_cast<const float4*>(&sW2T[j * 132 + tx * 4]);
#pragma unroll
            for (int i = 0; i < 4; i++) {
                float a = sH1[(ty * 4 + i) * 132 + j];
                h[c][i][0] += a * b.x; h[c][i][1] += a * b.y;
                h[c][i][2] += a * b.z; h[c][i][3] += a * b.w;
            }
        }
    }
#pragma unroll
    for (int i = 0; i < 4; i++) {
        float ss = 0.f;
#pragma unroll
        for (int c = 0; c < 2; c++)
#pragma unroll
            for (int k = 0; k < 4; k++) ss += h[c][i][k] * h[c][i][k];
#pragma unroll
        for (int o = 16; o; o >>= 1) ss += __shfl_xor_sync(0xffffffffu, ss, o);
        float inv = 1.f / fmaxf(sqrtf(ss), 1e-12f);
        int row = n0 + ty * 4 + i;
#pragma unroll
        for (int c = 0; c < 2; c++)
            *reinterpret_cast<float4*>(&g_hn[row * S0 + c * 128 + tx * 4]) =
                make_float4(h[c][i][0] * inv, h[c][i][1] * inv,
                            h[c][i][2] * inv, h[c][i][3] * inv);
    }
}

__global__ __launch_bounds__(256) void k_fused_a(
    const float* __restrict__ U0, const float* __restrict__ U1,
    const float* __restrict__ U2, const float* __restrict__ V2,
    const float* __restrict__ fc1w, const float* __restrict__ fc1b,
    const float* __restrict__ fc2w, const float* __restrict__ fc2b) {
    extern __shared__ float dsm[];
    int b = blockIdx.x;
    if (b < 256) body_factor(U0, U1, U2, dsm, b);
    else         body_proj(V2, fc1w, fc1b, fc2w, fc2b, dsm, b - 256);
}

// =================== fused layer B bodies ===================================

// across: C = A @ V2^T tile held in registers; epilogue dots with g_W2
// directly (no partial buffers) + fused sumsq(A).
__device__ __forceinline__ void body_across(const float* __restrict__ A,
                                            const float* __restrict__ V2,
                                            unsigned* dsmu, int bx, int by) {
    unsigned* sA = dsmu;                 // [128][RPAD]
    unsigned* sV = dsmu + 128 * RPAD;    // [64][RPAD]
    int t = threadIdx.x;
    int lane = t & 31, warp = t >> 5;
    int wi = warp >> 1, ws = warp & 1;
    int g = lane >> 2, q4 = lane & 3;
    int i0 = bx * 128;
    int jbeg = by * (N / 8);
    int jend = jbeg + (N / 8);

    float acc[2][4][4];
#pragma unroll
    for (int m = 0; m < 2; m++)
#pragma unroll
        for (int n = 0; n < 4; n++)
#pragma unroll
            for (int q = 0; q < 4; q++) acc[m][n][q] = 0.f;
    float ssq = 0.f;

    int lrow = t >> 1, lhalf = t & 1;
    for (int j0 = jbeg; j0 < jend; j0 += 32) {
#pragma unroll
        for (int q = 0; q < 4; q++) {
            int c = lhalf * 16 + q * 4;
            float4 v = *reinterpret_cast<const float4*>(A + (i0 + lrow) * N + j0 + c);
            ssq += v.x * v.x + v.y * v.y + v.z * v.z + v.w * v.w;
            sA[lrow * RPAD + c + 0] = f2tf32(v.x);
            sA[lrow * RPAD + c + 1] = f2tf32(v.y);
            sA[lrow * RPAD + c + 2] = f2tf32(v.z);
            sA[lrow * RPAD + c + 3] = f2tf32(v.w);
        }
#pragma unroll
        for (int q = 0; q < 2; q++) {
            int e = t * 2 + q;
            int r = e >> 3, c = (e & 7) * 4;
            float4 v = *reinterpret_cast<const float4*>(V2 + r * N + j0 + c);
            sV[r * RPAD + c + 0] = f2tf32(v.x);
            sV[r * RPAD + c + 1] = f2tf32(v.y);
            sV[r * RPAD + c + 2] = f2tf32(v.z);
            sV[r * RPAD + c + 3] = f2tf32(v.w);
        }
        __syncthreads();
#pragma unroll
        for (int ks = 0; ks < 4; ks++) {
            int kk = ks * 8;
            unsigned a[2][4], b[4][2];
#pragma unroll
            for (int m = 0; m < 2; m++) {
                int r = wi * 32 + m * 16;
                a[m][0] = sA[(r + g) * RPAD + kk + q4];
                a[m][1] = sA[(r + g + 8) * RPAD + kk + q4];
                a[m][2] = sA[(r + g) * RPAD + kk + q4 + 4];
                a[m][3] = sA[(r + g + 8) * RPAD + kk + q4 + 4];
            }
#pragma unroll
            for (int n = 0; n < 4; n++) {
                int c = ws * 32 + n * 8;
                b[n][0] = sV[(c + g) * RPAD + kk + q4];
                b[n][1] = sV[(c + g) * RPAD + kk + q4 + 4];
            }
#pragma unroll
            for (int m = 0; m < 2; m++)
#pragma unroll
                for (int n = 0; n < 4; n++)
                    mma_tf32(acc[m][n], a[m][0], a[m][1], a[m][2], a[m][3],
                             b[n][0], b[n][1]);
        }
        __syncthreads();
    }
    // epilogue: s1 = <acc tile, W2 tile> directly (no partial buffers)
    float s1 = 0.f;
#pragma unroll
    for (int m = 0; m < 2; m++) {
        int r0 = i0 + wi * 32 + m * 16 + g;
#pragma unroll
        for (int n = 0; n < 4; n++) {
            int c = ws * 32 + n * 8 + q4 * 2;
            float2 w0 = *reinterpret_cast<const float2*>(g_W2 + r0 * S2 + c);
            float2 w1 = *reinterpret_cast<const float2*>(g_W2 + (r0 + 8) * S2 + c);
            s1 += acc[m][n][0] * w0.x + acc[m][n][1] * w0.y
                + acc[m][n][2] * w1.x + acc[m][n][3] * w1.y;
        }
    }
    float bs1 = blockReduceSum(s1);
    float bs0 = blockReduceSum(ssq);
    if (t == 0) {
        atomicAdd(&g_acc[1], (double)bs1);
        atomicAdd(&g_acc[0], (double)bs0);
    }
}

// refl: symmetric — only upper-triangular tiles (528 of them). Off-diagonal
// tiles contribute to rows of BOTH tile-i and tile-j via column sums.
__device__ __forceinline__ void body_refl(const float* __restrict__ sim,
                                          unsigned* dsmu, int b2) {
    // decode triangular index -> (by, bx), by <= bx
    int r = 0, base = 0;
    while (base + (32 - r) <= b2) { base += 32 - r; r++; }
    int by = r, bx = r + (b2 - base);
    bool offdiag = (bx != by);

    unsigned* sI = dsmu;                 // [128][RPAD]
    unsigned* sJ = dsmu + 128 * RPAD;    // [128][RPAD]
    int t = threadIdx.x;
    int lane = t & 31, warp = t >> 5;
    int wi = warp >> 1, wj = warp & 1;
    int g = lane >> 2, q4 = lane & 3;
    int i0 = by * 128, j0 = bx * 128;

    float acc[2][8][4];
#pragma unroll
    for (int m = 0; m < 2; m++)
#pragma unroll
        for (int n = 0; n < 8; n++)
#pragma unroll
            for (int q = 0; q < 4; q++) acc[m][n][q] = 0.f;

    int lrow = t >> 1, lhalf = t & 1;
    for (int k0 = 0; k0 < S0; k0 += 32) {
#pragma unroll
        for (int q = 0; q < 4; q++) {
            int c = lhalf * 16 + q * 4;
            float4 v = *reinterpret_cast<const float4*>(g_hn + (i0 + lrow) * S0 + k0 + c);
            sI[lrow * RPAD + c + 0] = f2tf32(v.x);
            sI[lrow * RPAD + c + 1] = f2tf32(v.y);
            sI[lrow * RPAD + c + 2] = f2tf32(v.z);
            sI[lrow * RPAD + c + 3] = f2tf32(v.w);
            float4 w = *reinterpret_cast<const float4*>(g_hn + (j0 + lrow) * S0 + k0 + c);
            sJ[lrow * RPAD + c + 0] = f2tf32(w.x);
            sJ[lrow * RPAD + c + 1] = f2tf32(w.y);
            sJ[lrow * RPAD + c + 2] = f2tf32(w.z);
            sJ[lrow * RPAD + c + 3] = f2tf32(w.w);
        }
        __syncthreads();
#pragma unroll
        for (int ks = 0; ks < 4; ks++) {
            int kk = ks * 8;
            unsigned a[2][4], b[8][2];
#pragma unroll
            for (int m = 0; m < 2; m++) {
                int rr = wi * 32 + m * 16;
                a[m][0] = sI[(rr + g) * RPAD + kk + q4];
                a[m][1] = sI[(rr + g + 8) * RPAD + kk + q4];
                a[m][2] = sI[(rr + g) * RPAD + kk + q4 + 4];
                a[m][3] = sI[(rr + g + 8) * RPAD + kk + q4 + 4];
            }
#pragma unroll
            for (int n = 0; n < 8; n++) {
                int c = wj * 64 + n * 8;
                b[n][0] = sJ[(c + g) * RPAD + kk + q4];
                b[n][1] = sJ[(c + g) * RPAD + kk + q4 + 4];
            }
#pragma unroll
            for (int m = 0; m < 2; m++)
#pragma unroll
                for (int n = 0; n < 8; n++)
                    mma_tf32(acc[m][n], a[m][0], a[m][1], a[m][2], a[m][3],
                             b[n][0], b[n][1]);
        }
        __syncthreads();
    }

    // column accumulators (reuse smem arena; mainloop done after last sync)
    float* colT = reinterpret_cast<float*>(dsmu);        // [4][128]
    float* colP = reinterpret_cast<float*>(dsmu) + 512;  // [4][128]
    if (offdiag) {
        int cb = wj * 64;
        for (int x = lane; x < 64; x += 32) {
            colT[wi * 128 + cb + x] = 0.f;
            colP[wi * 128 + cb + x] = 0.f;
        }
        __syncwarp();
    }

#pragma unroll
    for (int m = 0; m < 2; m++) {
        float rs0 = 0.f, rs1 = 0.f, rp0 = 0.f, rp1 = 0.f;
        int r0 = i0 + wi * 32 + m * 16 + g;
#pragma unroll
        for (int n = 0; n < 8; n++) {
            int cl = wj * 64 + n * 8 + q4 * 2;
            int c = j0 + cl;
            float2 s0 = *reinterpret_cast<const float2*>(sim + r0 * N + c);
            float2 s1 = *reinterpret_cast<const float2*>(sim + (r0 + 8) * N + c);
            float e0 = __expf(2.f * acc[m][n][0]);
            float e1 = __expf(2.f * acc[m][n][1]);
            float e2 = __expf(2.f * acc[m][n][2]);
            float e3 = __expf(2.f * acc[m][n][3]);
            rs0 += e0 + e1;
            rs1 += e2 + e3;
            rp0 += (s0.x > 0.9f ? e0 : 0.f) + (s0.y > 0.9f ? e1 : 0.f);
            rp1 += (s1.x > 0.9f ? e2 : 0.f) + (s1.y > 0.9f ? e3 : 0.f);
            if (offdiag) {
                // column contributions: rows j0+cl(+1), masked by sim[j0+c][i0+r]
                float ct0 = e0 + e2, ct1 = e1 + e3;
                float st00 = sim[c * N + r0],       st01 = sim[c * N + r0 + 8];
                float st10 = sim[(c + 1) * N + r0], st11 = sim[(c + 1) * N + r0 + 8];
                float cp0 = (st00 > 0.9f ? e0 : 0.f) + (st01 > 0.9f ? e2 : 0.f);
                float cp1 = (st10 > 0.9f ? e1 : 0.f) + (st11 > 0.9f ? e3 : 0.f);
#pragma unroll
                for (int o = 4; o <= 16; o <<= 1) {
                    ct0 += __shfl_xor_sync(0xffffffffu, ct0, o);
                    ct1 += __shfl_xor_sync(0xffffffffu, ct1, o);
                    cp0 += __shfl_xor_sync(0xffffffffu, cp0, o);
                    cp1 += __shfl_xor_sync(0xffffffffu, cp1, o);
                }
                if (lane < 4) {   // g == 0, lane == q4
                    colT[wi * 128 + cl]     += ct0;
                    colT[wi * 128 + cl + 1] += ct1;
                    colP[wi * 128 + cl]     += cp0;
                    colP[wi * 128 + cl + 1] += cp1;
                }
            }
        }
        rs0 += __shfl_xor_sync(0xffffffffu, rs0, 1);
        rs0 += __shfl_xor_sync(0xffffffffu, rs0, 2);
        rs1 += __shfl_xor_sync(0xffffffffu, rs1, 1);
        rs1 += __shfl_xor_sync(0xffffffffu, rs1, 2);
        rp0 += __shfl_xor_sync(0xffffffffu, rp0, 1);
        rp0 += __shfl_xor_sync(0xffffffffu, rp0, 2);
        rp1 += __shfl_xor_sync(0xffffffffu, rp1, 1);
        rp1 += __shfl_xor_sync(0xffffffffu, rp1, 2);
        if (q4 == 0) {
            atomicAdd(&g_total [r0],     rs0);
            atomicAdd(&g_possim[r0],     rp0);
            atomicAdd(&g_total [r0 + 8], rs1);
            atomicAdd(&g_possim[r0 + 8], rp1);
        }
    }

    if (offdiag) {
        __syncthreads();
        if (t < 128) {
            float ctot = colT[t] + colT[128 + t] + colT[256 + t] + colT[384 + t];
            float cpos = colP[t] + colP[128 + t] + colP[256 + t] + colP[384 + t];
            atomicAdd(&g_total [j0 + t], ctot);
            atomicAdd(&g_possim[j0 + t], cpos);
        }
    }
}

__device__ __forceinline__ void body_gram1(float* sT, int bx) {
    int t = threadIdx.x;
    int k0 = bx * 32;
#pragma unroll
    for (int q = 0; q < 8; q++) {
        int e = t + q * 256;
        int r = e >> 6, c = e & 63;
        sT[r * 68 + c] = g_W2[(k0 + r) * S2 + c];
    }
    __syncthreads();
    int a = (t >> 4) * 4, b = (t & 15) * 4;
    float acc[4][4];
#pragma unroll
    for (int i = 0; i < 4; i++)
#pragma unroll
        for (int k = 0; k < 4; k++) acc[i][k] = 0.f;
#pragma unroll 4
    for (int r = 0; r < 32; r++) {
        float4 va = *reinterpret_cast<const float4*>(&sT[r * 68 + a]);
        float4 vb = *reinterpret_cast<const float4*>(&sT[r * 68 + b]);
        float av[4] = {va.x, va.y, va.z, va.w};
#pragma unroll
        for (int i = 0; i < 4; i++) {
            acc[i][0] += av[i] * vb.x; acc[i][1] += av[i] * vb.y;
            acc[i][2] += av[i] * vb.z; acc[i][3] += av[i] * vb.w;
        }
    }
#pragma unroll
    for (int i = 0; i < 4; i++)
#pragma unroll
        for (int k = 0; k < 4; k++)
            atomicAdd(&g_G1[(a + i) * S2 + b + k], acc[i][k]);
}

__device__ __forceinline__ void body_gram2(const float* __restrict__ V2,
                                           float* sT, int bx) {
    int t = threadIdx.x;
    int j0 = bx * 32;
#pragma unroll
    for (int q = 0; q < 8; q++) {
        int e = t + q * 256;
        int s = e >> 5, j = e & 31;
        sT[j * 68 + s] = V2[s * N + j0 + j];
    }
    __syncthreads();
    int a = (t >> 4) * 4, b = (t & 15) * 4;
    float acc[4][4];
#pragma unroll
    for (int i = 0; i < 4; i++)
#pragma unroll
        for (int k = 0; k < 4; k++) acc[i][k] = 0.f;
#pragma unroll 4
    for (int j = 0; j < 32; j++) {
        float4 va = *reinterpret_cast<const float4*>(&sT[j * 68 + a]);
        float4 vb = *reinterpret_cast<const float4*>(&sT[j * 68 + b]);
        float av[4] = {va.x, va.y, va.z, va.w};
#pragma unroll
        for (int i = 0; i < 4; i++) {
            acc[i][0] += av[i] * vb.x; acc[i][1] += av[i] * vb.y;
            acc[i][2] += av[i] * vb.z; acc[i][3] += av[i] * vb.w;
        }
    }
#pragma unroll
    for (int i = 0; i < 4; i++)
#pragma unroll
        for (int k = 0; k < 4; k++)
            atomicAdd(&g_G2[(a + i) * S2 + b + k], acc[i][k]);
}

__device__ __forceinline__ void body_loss5(const float* __restrict__ U0,
                                           const float* __restrict__ U1,
                                           const float* __restrict__ U2,
                                           const float* __restrict__ V2, int bx) {
    int tid = bx * 256 + threadIdx.x;
    int stride = 128 * 256;
    float s = 0.f;
    for (int i = tid; i < N * S0; i += stride) { float v = U0[i]; if (v < 0.f) s += v * v; }
    for (int i = tid; i < S0 * S1; i += stride) { float v = U1[i]; if (v < 0.f) s += v * v; }
    for (int i = tid; i < S1 * S2; i += stride) { float v = U2[i]; if (v < 0.f) s += v * v; }
    for (int i = tid; i < S2 * N; i += stride) { float v = V2[i]; if (v < 0.f) s += v * v; }
    float bs = blockReduceSum(s);
    if (threadIdx.x == 0) atomicAdd(&g_acc[3], (double)bs);
}

__device__ __forceinline__ void body_gather(const int* __restrict__ clq,
                                            const int* __restrict__ ngh, int bx) {
    int tid = bx * 256 + threadIdx.x;
    if (tid >= N * 24) return;
    int i = tid / 24, m = tid % 24;
    int j; float* out;
    if (m < 8) {
        j = clq[i * 8 + m];
        for (int p = 0; p < m; p++) if (clq[i * 8 + p] == j) return;  // set semantics
        out = g_posclq;
    } else {
        int mm = m - 8;
        j = ngh[i * 16 + mm];
        for (int p = 0; p < mm; p++) if (ngh[i * 16 + p] == j) return;
        out = g_posngh;
    }
    const float4* hi = reinterpret_cast<const float4*>(g_hn + i * S0);
    const float4* hj = reinterpret_cast<const float4*>(g_hn + j * S0);
    float d = 0.f;
#pragma unroll 8
    for (int s = 0; s < 64; s++) {
        float4 x = hi[s], y = hj[s];
        d += x.x * y.x + x.y * y.y + x.z * y.z + x.w * y.w;
    }
    atomicAdd(&out[i], expf(2.f * d));
}

// fused layer B: across[0,256) refl[256,784) gram1[784,912)
//                gram2[912,1040) loss5[1040,1168) gather[1168,1552)
__global__ __launch_bounds__(256) void k_fused_b(
    const float* __restrict__ A, const float* __restrict__ V2,
    const float* __restrict__ sim,
    const int* __restrict__ clq, const int* __restrict__ ngh,
    const float* __restrict__ U0, const float* __restrict__ U1,
    const float* __restrict__ U2) {
    extern __shared__ unsigned dsmu[];
    int b = blockIdx.x;
    if (b < 256) {
        body_across(A, V2, dsmu, b & 31, b >> 5);
    } else if (b < 784) {
        body_refl(sim, dsmu, b - 256);
    } else if (b < 912) {
        body_gram1(reinterpret_cast<float*>(dsmu), b - 784);
    } else if (b < 1040) {
        body_gram2(V2, reinterpret_cast<float*>(dsmu), b - 912);
    } else if (b < 1168) {
        body_loss5(U0, U1, U2, V2, b - 1040);
    } else {
        body_gather(clq, ngh, b - 1168);
    }
}

// =================== fused layer C: G1.G2 dot (8 blocks) + contrast (32) ====
__global__ __launch_bounds__(256) void k_fused_c() {
    int b = blockIdx.x;
    if (b < 8) {
        int tid = b * 256 + threadIdx.x;
        int stride = 8 * 256;
        float s2 = 0.f;
        for (int i = tid; i < S2 * S2; i += stride) s2 += g_G1[i] * g_G2[i];
        float b2 = blockReduceSum(s2);
        if (threadIdx.x == 0) atomicAdd(&g_acc[2], (double)b2);
    } else {
        int tid = (b - 8) * 256 + threadIdx.x;
        int stride = 32 * 256;
        float sc = 0.f, sn = 0.f, ssim = 0.f;
        for (int i = tid; i < N; i += stride) {
            float tot = g_total[i];
            float c1 = g_posclq[i] / tot;
            float c2 = g_posngh[i] / tot;
            float c3 = g_possim[i] / tot;
            if (c1 != 0.f) sc   -= logf(c1);
            if (c2 != 0.f) sn   -= logf(c2);
            if (c3 != 0.f) ssim -= logf(c3);
        }
        float b1 = blockReduceSum(sc);
        float b2 = blockReduceSum(sn);
        float b3 = blockReduceSum(ssim);
        if (threadIdx.x == 0) {
            atomicAdd(&g_acc[4], (double)b1);
            atomicAdd(&g_acc[5], (double)b2);
            atomicAdd(&g_acc[6], (double)b3);
        }
    }
}

// ---------------- final combine ---------------------------------------------
__global__ void k_final(float* out) {
    double l1 = g_acc[0] - 2.0 * g_acc[1] + g_acc[2];
    double l2 = g_acc[4] / (double)N;
    double l3 = g_acc[5] / (double)N;
    double l4 = g_acc[6] / (double)N;
    double l5 = g_acc[3];
    double tot = l1 + 0.1 * l2 + 0.1 * l3 + 0.1 * l4 + l5;
    out[0] = (float)tot; out[1] = (float)l1; out[2] = (float)l2;
    out[3] = (float)l3;  out[4] = (float)l4; out[5] = (float)l5;
}

// ---------------- launch -----------------------------------------------------
extern "C" void kernel_launch(void* const* d_in, const int* in_sizes, int n_in,
                              void* d_out, int out_size) {
    const float* A    = (const float*)d_in[0];
    const float* U0   = (const float*)d_in[1];
    const float* U1   = (const float*)d_in[2];
    const float* U2   = (const float*)d_in[3];
    const float* V2   = (const float*)d_in[4];
    const float* fc1w = (const float*)d_in[5];
    const float* fc1b = (const float*)d_in[6];
    const float* fc2w = (const float*)d_in[7];
    const float* fc2b = (const float*)d_in[8];
    const float* sim  = (const float*)d_in[9];
    const int*   clq  = (const int*)d_in[10];
    const int*   ngh  = (const int*)d_in[11];
    float* out = (float*)d_out;

    static bool attr_done = false;
    if (!attr_done) {
        cudaFuncSetAttribute(k_fused_a, cudaFuncAttributeMaxDynamicSharedMemorySize,
                             PROJ_SMEM_FLOATS * 4);
        attr_done = true;
    }

    k_zero<<<64, 256>>>();
    k_fused_a<<<384, 256, PROJ_SMEM_FLOATS * 4>>>(U0, U1, U2, V2,
                                                  fc1w, fc1b, fc2w, fc2b);
    k_fused_b<<<1552, 256, 2 * 128 * RPAD * 4>>>(A, V2, sim, clq, ngh, U0, U1, U2);
    k_fused_c<<<40, 256>>>();
    k_final<<<1, 1>>>(out);
}

// round 13
// speedup vs baseline: 6.4841x; 1.0379x over previous
#include <cuda_runtime.h>
#include <cuda_bf16.h>
#include <math.h>

#define N   4096
#define S0  256
#define S1  128
#define S2  64
#define RPAD 36
#define HPAD 20

// ---------------- scratch (device globals; no allocations allowed) ----------
__device__ __align__(16) float    g_W2[N * S2];    // (U0@U1)@U2          [N,64]
__device__ __align__(16) unsigned g_hnb[N * 128];  // hn as bf16x2 pairs  [N,256]
__device__ float g_G1[S2 * S2];                    // W2^T W2
__device__ float g_G2[S2 * S2];                    // V2 V2^T
__device__ float g_total [N];
__device__ float g_possim[N];
__device__ float g_posclq[N];
__device__ float g_posngh[N];
// 0: sumsq(A)  1: <W2, A V2^T>  2: (unused)  3: loss5
// 4: clique -log sum  5: neighbor -log sum  6: sim -log sum
__device__ double g_acc[8];

// ---------------- helpers ---------------------------------------------------
__device__ __forceinline__ float blockReduceSum(float v) {
    __shared__ float sh[33];
    int lane = threadIdx.x & 31, w = threadIdx.x >> 5;
#pragma unroll
    for (int o = 16; o; o >>= 1) v += __shfl_down_sync(0xffffffffu, v, o);
    if (lane == 0) sh[w] = v;
    __syncthreads();
    if (threadIdx.x == 0) {
        int nw = (blockDim.x + 31) >> 5;
        float r = 0.f;
        for (int x = 0; x < nw; x++) r += sh[x];
        sh[32] = r;
    }
    __syncthreads();
    float r = sh[32];
    __syncthreads();
    return r;
}

__device__ __forceinline__ unsigned f2tf32(float x) {
    unsigned r;
    asm("cvt.rna.tf32.f32 %0, %1;" : "=r"(r) : "f"(x));
    return r;
}

// pack two floats to bf16x2: lo in low 16 bits
__device__ __forceinline__ unsigned bf16pack(float lo, float hi) {
    unsigned r;
    asm("cvt.rn.bf16x2.f32 %0, %1, %2;" : "=r"(r) : "f"(hi), "f"(lo));
    return r;
}

__device__ __forceinline__ float2 bf2f(unsigned u) {
    __nv_bfloat162 h = *reinterpret_cast<__nv_bfloat162*>(&u);
    return make_float2(__low2float(h), __high2float(h));
}

__device__ __forceinline__ void mma_tf32(float* c,
                                         unsigned a0, unsigned a1, unsigned a2, unsigned a3,
                                         unsigned b0, unsigned b1) {
    asm volatile(
        "mma.sync.aligned.m16n8k8.row.col.f32.tf32.tf32.f32 "
        "{%0,%1,%2,%3},{%4,%5,%6,%7},{%8,%9},{%0,%1,%2,%3};"
        : "+f"(c[0]), "+f"(c[1]), "+f"(c[2]), "+f"(c[3])
        : "r"(a0), "r"(a1), "r"(a2), "r"(a3), "r"(b0), "r"(b1));
}

__device__ __forceinline__ void mma_bf16(float* c,
                                         unsigned a0, unsigned a1, unsigned a2, unsigned a3,
                                         unsigned b0, unsigned b1) {
    asm volatile(
        "mma.sync.aligned.m16n8k16.row.col.f32.bf16.bf16.f32 "
        "{%0,%1,%2,%3},{%4,%5,%6,%7},{%8,%9},{%0,%1,%2,%3};"
        : "+f"(c[0]), "+f"(c[1]), "+f"(c[2]), "+f"(c[3])
        : "r"(a0), "r"(a1), "r"(a2), "r"(a3), "r"(b0), "r"(b1));
}

// ---------------- zero scratch ----------------------------------------------
__global__ void k_zero() {
    int tid = blockIdx.x * blockDim.x + threadIdx.x;
    int stride = gridDim.x * blockDim.x;
    for (int i = tid; i < S2 * S2; i += stride) { g_G1[i] = 0.f; g_G2[i] = 0.f; }
    for (int i = tid; i < N; i += stride) {
        g_total[i] = 0.f; g_possim[i] = 0.f; g_posclq[i] = 0.f; g_posngh[i] = 0.f;
    }
    if (tid < 8) g_acc[tid] = 0.0;
}

// =================== fused layer A: factor (256 blocks) + proj (128) ========
#define PROJ_SMEM_FLOATS 21120

__device__ __forceinline__ void body_factor(const float* __restrict__ U0,
                                            const float* __restrict__ U1,
                                            const float* __restrict__ U2,
                                            float* dsm, int bx) {
    float* sU0 = dsm;            // [16][256]
    float* sU1 = dsm + 4096;     // [32][132]
    float* sW1 = dsm + 8320;     // [16][132]
    int t = threadIdx.x;
    int i0 = bx * 16;
#pragma unroll
    for (int q = 0; q < 16; q++) {
        int e = t + q * 256;
        int r = e >> 8, k = e & 255;
        sU0[r * 256 + k] = U0[(i0 + r) * S0 + k];
    }
    int ty = t >> 5, tx = t & 31;
    float accw[2][4];
#pragma unroll
    for (int i = 0; i < 2; i++)
#pragma unroll
        for (int k = 0; k < 4; k++) accw[i][k] = 0.f;
    for (int k0 = 0; k0 < S0; k0 += 32) {
        __syncthreads();
#pragma unroll
        for (int q = 0; q < 16; q++) {
            int e = t + q * 256;
            int kk = e >> 7, j = e & 127;
            sU1[kk * 132 + j] = U1[(k0 + kk) * S1 + j];
        }
        __syncthreads();
#pragma unroll
        for (int kk = 0; kk < 32; kk++) {
            float4 b = *reinterpret_cast<const float4*>(&sU1[kk * 132 + tx * 4]);
            float a0 = sU0[(ty * 2 + 0) * 256 + k0 + kk];
            float a1 = sU0[(ty * 2 + 1) * 256 + k0 + kk];
            accw[0][0] += a0 * b.x; accw[0][1] += a0 * b.y;
            accw[0][2] += a0 * b.z; accw[0][3] += a0 * b.w;
            accw[1][0] += a1 * b.x; accw[1][1] += a1 * b.y;
            accw[1][2] += a1 * b.z; accw[1][3] += a1 * b.w;
        }
    }
    __syncthreads();
#pragma unroll
    for (int i = 0; i < 2; i++)
        *reinterpret_cast<float4*>(&sW1[(ty * 2 + i) * 132 + tx * 4]) =
            make_float4(accw[i][0], accw[i][1], accw[i][2], accw[i][3]);
    __syncthreads();
    int tn = t >> 4, tc = t & 15;
    float acc2[4] = {0.f, 0.f, 0.f, 0.f};
#pragma unroll 4
    for (int k = 0; k < S1; k++) {
        float a = sW1[tn * 132 + k];
        float4 b = *reinterpret_cast<const float4*>(&U2[k * S2 + tc * 4]);
        acc2[0] += a * b.x; acc2[1] += a * b.y;
        acc2[2] += a * b.z; acc2[3] += a * b.w;
    }
    *reinterpret_cast<float4*>(&g_W2[(i0 + tn) * S2 + tc * 4]) =
        make_float4(acc2[0], acc2[1], acc2[2], acc2[3]);
}

__device__ __forceinline__ void body_proj(const float* __restrict__ V2,
                                          const float* __restrict__ fc1w,
                                          const float* __restrict__ fc1b,
                                          const float* __restrict__ fc2w,
                                          const float* __restrict__ fc2b,
                                          float* dsm, int bx) {
    float* sXT  = dsm;           // [64][40]
    float* sW1T = dsm + 2560;    // [64][132]
    float* sW2T = dsm;           // [128][132] (stage 2, aliases stage-1 arrays)
    float* sH1  = dsm + 16896;   // [32][132]
    int t = threadIdx.x;
    int n0 = bx * 32;
    int ty = t >> 5, tx = t & 31;

#pragma unroll
    for (int q = 0; q < 8; q++) {
        int e = t + q * 256;
        int s = e >> 5, n = e & 31;
        sXT[s * 40 + n] = V2[s * N + n0 + n];
    }
#pragma unroll
    for (int q = 0; q < 32; q++) {
        int e = t + q * 256;
        int j = e >> 6, s = e & 63;
        sW1T[s * 132 + j] = fc1w[e];
    }
    __syncthreads();

    float4 b1v = *reinterpret_cast<const float4*>(&fc1b[tx * 4]);
    float acc1[4][4];
#pragma unroll
    for (int i = 0; i < 4; i++) {
        acc1[i][0] = b1v.x; acc1[i][1] = b1v.y;
        acc1[i][2] = b1v.z; acc1[i][3] = b1v.w;
    }
#pragma unroll 4
    for (int s = 0; s < S2; s++) {
        float4 a = *reinterpret_cast<const float4*>(&sXT[s * 40 + ty * 4]);
        float4 b = *reinterpret_cast<const float4*>(&sW1T[s * 132 + tx * 4]);
        float av[4] = {a.x, a.y, a.z, a.w};
#pragma unroll
        for (int i = 0; i < 4; i++) {
            acc1[i][0] += av[i] * b.x; acc1[i][1] += av[i] * b.y;
            acc1[i][2] += av[i] * b.z; acc1[i][3] += av[i] * b.w;
        }
    }
#pragma unroll
    for (int i = 0; i < 4; i++) {
        float4 h;
        h.x = acc1[i][0] > 0.f ? acc1[i][0] : expm1f(acc1[i][0]);
        h.y = acc1[i][1] > 0.f ? acc1[i][1] : expm1f(acc1[i][1]);
        h.z = acc1[i][2] > 0.f ? acc1[i][2] : expm1f(acc1[i][2]);
        h.w = acc1[i][3] > 0.f ? acc1[i][3] : expm1f(acc1[i][3]);
        *reinterpret_cast<float4*>(&sH1[(ty * 4 + i) * 132 + tx * 4]) = h;
    }

    float h[2][4][4];
#pragma unroll
    for (int c = 0; c < 2; c++) {
        __syncthreads();
#pragma unroll
        for (int q = 0; q < 64; q++) {
            int e = t + q * 256;
            int lt = e >> 7, j = e & 127;
            sW2T[j * 132 + lt] = fc2w[(c * 128 + lt) * S1 + j];
        }
        __syncthreads();
        float4 b2v = *reinterpret_cast<const float4*>(&fc2b[c * 128 + tx * 4]);
#pragma unroll
        for (int i = 0; i < 4; i++) {
            h[c][i][0] = b2v.x; h[c][i][1] = b2v.y;
            h[c][i][2] = b2v.z; h[c][i][3] = b2v.w;
        }
#pragma unroll 4
        for (int j = 0; j < S1; j++) {
            float4 b = *reinterpret_cast<const float4*>(&sW2T[j * 132 + tx * 4]);
#pragma unroll
            for (int i = 0; i < 4; i++) {
                float a = sH1[(ty * 4 + i) * 132 + j];
                h[c][i][0] += a * b.x; h[c][i][1] += a * b.y;
                h[c][i][2] += a * b.z; h[c][i][3] += a * b.w;
            }
        }
    }
#pragma unroll
    for (int i = 0; i < 4; i++) {
        float ss = 0.f;
#pragma unroll
        for (int c = 0; c < 2; c++)
#pragma unroll
            for (int k = 0; k < 4; k++) ss += h[c][i][k] * h[c][i][k];
#pragma unroll
        for (int o = 16; o; o >>= 1) ss += __shfl_xor_sync(0xffffffffu, ss, o);
        float inv = 1.f / fmaxf(sqrtf(ss), 1e-12f);
        int row = n0 + ty * 4 + i;
#pragma unroll
        for (int c = 0; c < 2; c++) {
            unsigned p0 = bf16pack(h[c][i][0] * inv, h[c][i][1] * inv);
            unsigned p1 = bf16pack(h[c][i][2] * inv, h[c][i][3] * inv);
            *reinterpret_cast<uint2*>(&g_hnb[row * 128 + c * 64 + tx * 2]) =
                make_uint2(p0, p1);
        }
    }
}

__global__ __launch_bounds__(256) void k_fused_a(
    const float* __restrict__ U0, const float* __restrict__ U1,
    const float* __restrict__ U2, const float* __restrict__ V2,
    const float* __restrict__ fc1w, const float* __restrict__ fc1b,
    const float* __restrict__ fc2w, const float* __restrict__ fc2b) {
    extern __shared__ float dsm[];
    int b = blockIdx.x;
    if (b < 256) body_factor(U0, U1, U2, dsm, b);
    else         body_proj(V2, fc1w, fc1b, fc2w, fc2b, dsm, b - 256);
}

// =================== fused layer B bodies ===================================

// across: C = A @ V2^T tile held in registers; epilogue dots with g_W2
// directly (no partial buffers) + fused sumsq(A).
__device__ __forceinline__ void body_across(const float* __restrict__ A,
                                            const float* __restrict__ V2,
                                            unsigned* dsmu, int bx, int by) {
    unsigned* sA = dsmu;                 // [128][RPAD]
    unsigned* sV = dsmu + 128 * RPAD;    // [64][RPAD]
    int t = threadIdx.x;
    int lane = t & 31, warp = t >> 5;
    int wi = warp >> 1, ws = warp & 1;
    int g = lane >> 2, q4 = lane & 3;
    int i0 = bx * 128;
    int jbeg = by * (N / 8);
    int jend = jbeg + (N / 8);

    float acc[2][4][4];
#pragma unroll
    for (int m = 0; m < 2; m++)
#pragma unroll
        for (int n = 0; n < 4; n++)
#pragma unroll
            for (int q = 0; q < 4; q++) acc[m][n][q] = 0.f;
    float ssq = 0.f;

    int lrow = t >> 1, lhalf = t & 1;
    for (int j0 = jbeg; j0 < jend; j0 += 32) {
#pragma unroll
        for (int q = 0; q < 4; q++) {
            int c = lhalf * 16 + q * 4;
            float4 v = *reinterpret_cast<const float4*>(A + (i0 + lrow) * N + j0 + c);
            ssq += v.x * v.x + v.y * v.y + v.z * v.z + v.w * v.w;
            sA[lrow * RPAD + c + 0] = f2tf32(v.x);
            sA[lrow * RPAD + c + 1] = f2tf32(v.y);
            sA[lrow * RPAD + c + 2] = f2tf32(v.z);
            sA[lrow * RPAD + c + 3] = f2tf32(v.w);
        }
#pragma unroll
        for (int q = 0; q < 2; q++) {
            int e = t * 2 + q;
            int r = e >> 3, c = (e & 7) * 4;
            float4 v = *reinterpret_cast<const float4*>(V2 + r * N + j0 + c);
            sV[r * RPAD + c + 0] = f2tf32(v.x);
            sV[r * RPAD + c + 1] = f2tf32(v.y);
            sV[r * RPAD + c + 2] = f2tf32(v.z);
            sV[r * RPAD + c + 3] = f2tf32(v.w);
        }
        __syncthreads();
#pragma unroll
        for (int ks = 0; ks < 4; ks++) {
            int kk = ks * 8;
            unsigned a[2][4], b[4][2];
#pragma unroll
            for (int m = 0; m < 2; m++) {
                int r = wi * 32 + m * 16;
                a[m][0] = sA[(r + g) * RPAD + kk + q4];
                a[m][1] = sA[(r + g + 8) * RPAD + kk + q4];
                a[m][2] = sA[(r + g) * RPAD + kk + q4 + 4];
                a[m][3] = sA[(r + g + 8) * RPAD + kk + q4 + 4];
            }
#pragma unroll
            for (int n = 0; n < 4; n++) {
                int c = ws * 32 + n * 8;
                b[n][0] = sV[(c + g) * RPAD + kk + q4];
                b[n][1] = sV[(c + g) * RPAD + kk + q4 + 4];
            }
#pragma unroll
            for (int m = 0; m < 2; m++)
#pragma unroll
                for (int n = 0; n < 4; n++)
                    mma_tf32(acc[m][n], a[m][0], a[m][1], a[m][2], a[m][3],
                             b[n][0], b[n][1]);
        }
        __syncthreads();
    }
    float s1 = 0.f;
#pragma unroll
    for (int m = 0; m < 2; m++) {
        int r0 = i0 + wi * 32 + m * 16 + g;
#pragma unroll
        for (int n = 0; n < 4; n++) {
            int c = ws * 32 + n * 8 + q4 * 2;
            float2 w0 = *reinterpret_cast<const float2*>(g_W2 + r0 * S2 + c);
            float2 w1 = *reinterpret_cast<const float2*>(g_W2 + (r0 + 8) * S2 + c);
            s1 += acc[m][n][0] * w0.x + acc[m][n][1] * w0.y
                + acc[m][n][2] * w1.x + acc[m][n][3] * w1.y;
        }
    }
    float bs1 = blockReduceSum(s1);
    float bs0 = blockReduceSum(ssq);
    if (t == 0) {
        atomicAdd(&g_acc[1], (double)bs1);
        atomicAdd(&g_acc[0], (double)bs0);
    }
}

// refl: bf16 m16n8k16, symmetric upper-triangular tiles (528 blocks).
__device__ __forceinline__ void body_refl(const float* __restrict__ sim,
                                          unsigned* dsmu, int b2) {
    // decode triangular index -> (by, bx), by <= bx
    int r = 0, base = 0;
    while (base + (32 - r) <= b2) { base += 32 - r; r++; }
    int by = r, bx = r + (b2 - base);
    bool offdiag = (bx != by);

    unsigned* sI = dsmu;                 // [128][HPAD] bf16x2 pairs
    unsigned* sJ = dsmu + 128 * HPAD;
    int t = threadIdx.x;
    int lane = t & 31, warp = t >> 5;
    int wi = warp >> 1, wj = warp & 1;
    int g = lane >> 2, q4 = lane & 3;
    int i0 = by * 128, j0 = bx * 128;

    float acc[2][8][4];
#pragma unroll
    for (int m = 0; m < 2; m++)
#pragma unroll
        for (int n = 0; n < 8; n++)
#pragma unroll
            for (int q = 0; q < 4; q++) acc[m][n][q] = 0.f;

    int lrow = t >> 1, lhalf = t & 1;
    for (int kp = 0; kp < 128; kp += 16) {       // pair index; k step 32
        {
            const unsigned* src = g_hnb + (i0 + lrow) * 128 + kp + lhalf * 8;
            uint4 v0 = *reinterpret_cast<const uint4*>(src);
            uint4 v1 = *reinterpret_cast<const uint4*>(src + 4);
            *reinterpret_cast<uint4*>(sI + lrow * HPAD + lhalf * 8)     = v0;
            *reinterpret_cast<uint4*>(sI + lrow * HPAD + lhalf * 8 + 4) = v1;
            const unsigned* srj = g_hnb + (j0 + lrow) * 128 + kp + lhalf * 8;
            uint4 w0 = *reinterpret_cast<const uint4*>(srj);
            uint4 w1 = *reinterpret_cast<const uint4*>(srj + 4);
            *reinterpret_cast<uint4*>(sJ + lrow * HPAD + lhalf * 8)     = w0;
            *reinterpret_cast<uint4*>(sJ + lrow * HPAD + lhalf * 8 + 4) = w1;
        }
        __syncthreads();
#pragma unroll
        for (int ks = 0; ks < 2; ks++) {         // two k16 mma steps
            int kk = ks * 8;                     // pair offset
            unsigned a[2][4], b[8][2];
#pragma unroll
            for (int m = 0; m < 2; m++) {
                int rr = wi * 32 + m * 16;
                a[m][0] = sI[(rr + g) * HPAD + kk + q4];
                a[m][1] = sI[(rr + g + 8) * HPAD + kk + q4];
                a[m][2] = sI[(rr + g) * HPAD + kk + q4 + 4];
                a[m][3] = sI[(rr + g + 8) * HPAD + kk + q4 + 4];
            }
#pragma unroll
            for (int n = 0; n < 8; n++) {
                int c = wj * 64 + n * 8;
                b[n][0] = sJ[(c + g) * HPAD + kk + q4];
                b[n][1] = sJ[(c + g) * HPAD + kk + q4 + 4];
            }
#pragma unroll
            for (int m = 0; m < 2; m++)
#pragma unroll
                for (int n = 0; n < 8; n++)
                    mma_bf16(acc[m][n], a[m][0], a[m][1], a[m][2], a[m][3],
                             b[n][0], b[n][1]);
        }
        __syncthreads();
    }

    // column accumulators (reuse smem arena; mainloop done after last sync)
    float* colT = reinterpret_cast<float*>(dsmu);        // [4][128]
    float* colP = reinterpret_cast<float*>(dsmu) + 512;  // [4][128]
    if (offdiag) {
        int cb = wj * 64;
        for (int x = lane; x < 64; x += 32) {
            colT[wi * 128 + cb + x] = 0.f;
            colP[wi * 128 + cb + x] = 0.f;
        }
        __syncwarp();
    }

#pragma unroll
    for (int m = 0; m < 2; m++) {
        float rs0 = 0.f, rs1 = 0.f, rp0 = 0.f, rp1 = 0.f;
        int r0 = i0 + wi * 32 + m * 16 + g;
#pragma unroll
        for (int n = 0; n < 8; n++) {
            int cl = wj * 64 + n * 8 + q4 * 2;
            int c = j0 + cl;
            float2 s0 = *reinterpret_cast<const float2*>(sim + r0 * N + c);
            float2 s1 = *reinterpret_cast<const float2*>(sim + (r0 + 8) * N + c);
            float e0 = __expf(2.f * acc[m][n][0]);
            float e1 = __expf(2.f * acc[m][n][1]);
            float e2 = __expf(2.f * acc[m][n][2]);
            float e3 = __expf(2.f * acc[m][n][3]);
            rs0 += e0 + e1;
            rs1 += e2 + e3;
            rp0 += (s0.x > 0.9f ? e0 : 0.f) + (s0.y > 0.9f ? e1 : 0.f);
            rp1 += (s1.x > 0.9f ? e2 : 0.f) + (s1.y > 0.9f ? e3 : 0.f);
            if (offdiag) {
                float ct0 = e0 + e2, ct1 = e1 + e3;
                float st00 = sim[c * N + r0],       st01 = sim[c * N + r0 + 8];
                float st10 = sim[(c + 1) * N + r0], st11 = sim[(c + 1) * N + r0 + 8];
                float cp0 = (st00 > 0.9f ? e0 : 0.f) + (st01 > 0.9f ? e2 : 0.f);
                float cp1 = (st10 > 0.9f ? e1 : 0.f) + (st11 > 0.9f ? e3 : 0.f);
#pragma unroll
                for (int o = 4; o <= 16; o <<= 1) {
                    ct0 += __shfl_xor_sync(0xffffffffu, ct0, o);
                    ct1 += __shfl_xor_sync(0xffffffffu, ct1, o);
                    cp0 += __shfl_xor_sync(0xffffffffu, cp0, o);
                    cp1 += __shfl_xor_sync(0xffffffffu, cp1, o);
                }
                if (lane < 4) {   // g == 0, lane == q4
                    colT[wi * 128 + cl]     += ct0;
                    colT[wi * 128 + cl + 1] += ct1;
                    colP[wi * 128 + cl]     += cp0;
                    colP[wi * 128 + cl + 1] += cp1;
                }
            }
        }
        rs0 += __shfl_xor_sync(0xffffffffu, rs0, 1);
        rs0 += __shfl_xor_sync(0xffffffffu, rs0, 2);
        rs1 += __shfl_xor_sync(0xffffffffu, rs1, 1);
        rs1 += __shfl_xor_sync(0xffffffffu, rs1, 2);
        rp0 += __shfl_xor_sync(0xffffffffu, rp0, 1);
        rp0 += __shfl_xor_sync(0xffffffffu, rp0, 2);
        rp1 += __shfl_xor_sync(0xffffffffu, rp1, 1);
        rp1 += __shfl_xor_sync(0xffffffffu, rp1, 2);
        if (q4 == 0) {
            atomicAdd(&g_total [r0],     rs0);
            atomicAdd(&g_possim[r0],     rp0);
            atomicAdd(&g_total [r0 + 8], rs1);
            atomicAdd(&g_possim[r0 + 8], rp1);
        }
    }

    if (offdiag) {
        __syncthreads();
        if (t < 128) {
            float ctot = colT[t] + colT[128 + t] + colT[256 + t] + colT[384 + t];
            float cpos = colP[t] + colP[128 + t] + colP[256 + t] + colP[384 + t];
            atomicAdd(&g_total [j0 + t], ctot);
            atomicAdd(&g_possim[j0 + t], cpos);
        }
    }
}

__device__ __forceinline__ void body_gram1(float* sT, int bx) {
    int t = threadIdx.x;
    int k0 = bx * 32;
#pragma unroll
    for (int q = 0; q < 8; q++) {
        int e = t + q * 256;
        int r = e >> 6, c = e & 63;
        sT[r * 68 + c] = g_W2[(k0 + r) * S2 + c];
    }
    __syncthreads();
    int a = (t >> 4) * 4, b = (t & 15) * 4;
    float acc[4][4];
#pragma unroll
    for (int i = 0; i < 4; i++)
#pragma unroll
        for (int k = 0; k < 4; k++) acc[i][k] = 0.f;
#pragma unroll 4
    for (int r = 0; r < 32; r++) {
        float4 va = *reinterpret_cast<const float4*>(&sT[r * 68 + a]);
        float4 vb = *reinterpret_cast<const float4*>(&sT[r * 68 + b]);
        float av[4] = {va.x, va.y, va.z, va.w};
#pragma unroll
        for (int i = 0; i < 4; i++) {
            acc[i][0] += av[i] * vb.x; acc[i][1] += av[i] * vb.y;
            acc[i][2] += av[i] * vb.z; acc[i][3] += av[i] * vb.w;
        }
    }
#pragma unroll
    for (int i = 0; i < 4; i++)
#pragma unroll
        for (int k = 0; k < 4; k++)
            atomicAdd(&g_G1[(a + i) * S2 + b + k], acc[i][k]);
}

__device__ __forceinline__ void body_gram2(const float* __restrict__ V2,
                                           float* sT, int bx) {
    int t = threadIdx.x;
    int j0 = bx * 32;
#pragma unroll
    for (int q = 0; q < 8; q++) {
        int e = t + q * 256;
        int s = e >> 5, j = e & 31;
        sT[j * 68 + s] = V2[s * N + j0 + j];
    }
    __syncthreads();
    int a = (t >> 4) * 4, b = (t & 15) * 4;
    float acc[4][4];
#pragma unroll
    for (int i = 0; i < 4; i++)
#pragma unroll
        for (int k = 0; k < 4; k++) acc[i][k] = 0.f;
#pragma unroll 4
    for (int j = 0; j < 32; j++) {
        float4 va = *reinterpret_cast<const float4*>(&sT[j * 68 + a]);
        float4 vb = *reinterpret_cast<const float4*>(&sT[j * 68 + b]);
        float av[4] = {va.x, va.y, va.z, va.w};
#pragma unroll
        for (int i = 0; i < 4; i++) {
            acc[i][0] += av[i] * vb.x; acc[i][1] += av[i] * vb.y;
            acc[i][2] += av[i] * vb.z; acc[i][3] += av[i] * vb.w;
        }
    }
#pragma unroll
    for (int i = 0; i < 4; i++)
#pragma unroll
        for (int k = 0; k < 4; k++)
            atomicAdd(&g_G2[(a + i) * S2 + b + k], acc[i][k]);
}

__device__ __forceinline__ void body_loss5(const float* __restrict__ U0,
                                           const float* __restrict__ U1,
                                           const float* __restrict__ U2,
                                           const float* __restrict__ V2, int bx) {
    int tid = bx * 256 + threadIdx.x;
    int stride = 128 * 256;
    float s = 0.f;
    for (int i = tid; i < N * S0; i += stride) { float v = U0[i]; if (v < 0.f) s += v * v; }
    for (int i = tid; i < S0 * S1; i += stride) { float v = U1[i]; if (v < 0.f) s += v * v; }
    for (int i = tid; i < S1 * S2; i += stride) { float v = U2[i]; if (v < 0.f) s += v * v; }
    for (int i = tid; i < S2 * N; i += stride) { float v = V2[i]; if (v < 0.f) s += v * v; }
    float bs = blockReduceSum(s);
    if (threadIdx.x == 0) atomicAdd(&g_acc[3], (double)bs);
}

__device__ __forceinline__ void body_gather(const int* __restrict__ clq,
                                            const int* __restrict__ ngh, int bx) {
    int tid = bx * 256 + threadIdx.x;
    if (tid >= N * 24) return;
    int i = tid / 24, m = tid % 24;
    int j; float* out;
    if (m < 8) {
        j = clq[i * 8 + m];
        for (int p = 0; p < m; p++) if (clq[i * 8 + p] == j) return;  // set semantics
        out = g_posclq;
    } else {
        int mm = m - 8;
        j = ngh[i * 16 + mm];
        for (int p = 0; p < mm; p++) if (ngh[i * 16 + p] == j) return;
        out = g_posngh;
    }
    const uint4* hi = reinterpret_cast<const uint4*>(g_hnb + i * 128);
    const uint4* hj = reinterpret_cast<const uint4*>(g_hnb + j * 128);
    float d = 0.f;
#pragma unroll 8
    for (int s = 0; s < 32; s++) {
        uint4 x = hi[s], y = hj[s];
        float2 a0 = bf2f(x.x), b0 = bf2f(y.x);
        float2 a1 = bf2f(x.y), b1 = bf2f(y.y);
        float2 a2 = bf2f(x.z), b2 = bf2f(y.z);
        float2 a3 = bf2f(x.w), b3 = bf2f(y.w);
        d += a0.x * b0.x + a0.y * b0.y + a1.x * b1.x + a1.y * b1.y
           + a2.x * b2.x + a2.y * b2.y + a3.x * b3.x + a3.y * b3.y;
    }
    atomicAdd(&out[i], expf(2.f * d));
}

// fused layer B: across[0,256) refl[256,784) gram1[784,912)
//                gram2[912,1040) loss5[1040,1168) gather[1168,1552)
__global__ __launch_bounds__(256) void k_fused_b(
    const float* __restrict__ A, const float* __restrict__ V2,
    const float* __restrict__ sim,
    const int* __restrict__ clq, const int* __restrict__ ngh,
    const float* __restrict__ U0, const float* __restrict__ U1,
    const float* __restrict__ U2) {
    extern __shared__ unsigned dsmu[];
    int b = blockIdx.x;
    if (b < 256) {
        body_across(A, V2, dsmu, b & 31, b >> 5);
    } else if (b < 784) {
        body_refl(sim, dsmu, b - 256);
    } else if (b < 912) {
        body_gram1(reinterpret_cast<float*>(dsmu), b - 784);
    } else if (b < 1040) {
        body_gram2(V2, reinterpret_cast<float*>(dsmu), b - 912);
    } else if (b < 1168) {
        body_loss5(U0, U1, U2, V2, b - 1040);
    } else {
        body_gather(clq, ngh, b - 1168);
    }
}

// ========= final: G1.G2 dot + contrast + combine (single 256-thread block) ==
__global__ __launch_bounds__(256) void k_final(float* out) {
    int t = threadIdx.x;
    float s2 = 0.f;
    for (int i = t; i < S2 * S2; i += 256) s2 += g_G1[i] * g_G2[i];
    float sc = 0.f, sn = 0.f, ssim = 0.f;
    for (int i = t; i < N; i += 256) {
        float tot = g_total[i];
        float c1 = g_posclq[i] / tot;
        float c2 = g_posngh[i] / tot;
        float c3 = g_possim[i] / tot;
        if (c1 != 0.f) sc   -= logf(c1);
        if (c2 != 0.f) sn   -= logf(c2);
        if (c3 != 0.f) ssim -= logf(c3);
    }
    float b2 = blockReduceSum(s2);
    float b4 = blockReduceSum(sc);
    float b5 = blockReduceSum(sn);
    float b6 = blockReduceSum(ssim);
    if (t == 0) {
        double l1 = g_acc[0] - 2.0 * g_acc[1] + (double)b2;
        double l2 = (double)b4 / (double)N;
        double l3 = (double)b5 / (double)N;
        double l4 = (double)b6 / (double)N;
        double l5 = g_acc[3];
        double tot = l1 + 0.1 * l2 + 0.1 * l3 + 0.1 * l4 + l5;
        out[0] = (float)tot; out[1] = (float)l1; out[2] = (float)l2;
        out[3] = (float)l3;  out[4] = (float)l4; out[5] = (float)l5;
    }
}

// ---------------- launch -----------------------------------------------------
extern "C" void kernel_launch(void* const* d_in, const int* in_sizes, int n_in,
                              void* d_out, int out_size) {
    const float* A    = (const float*)d_in[0];
    const float* U0   = (const float*)d_in[1];
    const float* U1   = (const float*)d_in[2];
    const float* U2   = (const float*)d_in[3];
    const float* V2   = (const float*)d_in[4];
    const float* fc1w = (const float*)d_in[5];
    const float* fc1b = (const float*)d_in[6];
    const float* fc2w = (const float*)d_in[7];
    const float* fc2b = (const float*)d_in[8];
    const float* sim  = (const float*)d_in[9];
    const int*   clq  = (const int*)d_in[10];
    const int*   ngh  = (const int*)d_in[11];
    float* out = (float*)d_out;

    static bool attr_done = false;
    if (!attr_done) {
        cudaFuncSetAttribute(k_fused_a, cudaFuncAttributeMaxDynamicSharedMemorySize,
                             PROJ_SMEM_FLOATS * 4);
        attr_done = true;
    }

    k_zero<<<64, 256>>>();
    k_fused_a<<<384, 256, PROJ_SMEM_FLOATS * 4>>>(U0, U1, U2, V2,
                                                  fc1w, fc1b, fc2w, fc2b);
    k_fused_b<<<1552, 256, (128 + 64) * RPAD * 4>>>(A, V2, sim, clq, ngh, U0, U1, U2);
    k_final<<<1, 256>>>(out);
}

// round 15
// speedup vs baseline: 7.6218x; 1.1755x over previous
#include <cuda_runtime.h>
#include <cuda_bf16.h>
#include <math.h>

#define N   4096
#define S0  256
#define S1  128
#define S2  64
#define RPAD 36
#define HPAD 20

// ---------------- scratch (device globals; no allocations allowed) ----------
__device__ __align__(16) float    g_W2[N * S2];    // (U0@U1)@U2          [N,64]
__device__ __align__(16) unsigned g_hnb[N * 128];  // hn as bf16x2 pairs  [N,256]
__device__ float g_G1[S2 * S2];                    // W2^T W2
__device__ float g_G2[S2 * S2];                    // V2 V2^T
__device__ float g_total [N];
__device__ float g_possim[N];
__device__ float g_posclq[N];
__device__ float g_posngh[N];
// 0: sumsq(A)  1: <W2, A V2^T>  2: <G1,G2>  3: loss5
// 4: clique -log sum  5: neighbor -log sum  6: sim -log sum
__device__ double g_acc[8];

// ---------------- helpers ---------------------------------------------------
__device__ __forceinline__ float blockReduceSum(float v) {
    __shared__ float sh[33];
    int lane = threadIdx.x & 31, w = threadIdx.x >> 5;
#pragma unroll
    for (int o = 16; o; o >>= 1) v += __shfl_down_sync(0xffffffffu, v, o);
    if (lane == 0) sh[w] = v;
    __syncthreads();
    if (threadIdx.x == 0) {
        int nw = (blockDim.x + 31) >> 5;
        float r = 0.f;
        for (int x = 0; x < nw; x++) r += sh[x];
        sh[32] = r;
    }
    __syncthreads();
    float r = sh[32];
    __syncthreads();
    return r;
}

__device__ __forceinline__ unsigned f2tf32(float x) {
    unsigned r;
    asm("cvt.rna.tf32.f32 %0, %1;" : "=r"(r) : "f"(x));
    return r;
}

// pack two floats to bf16x2: lo in low 16 bits
__device__ __forceinline__ unsigned bf16pack(float lo, float hi) {
    unsigned r;
    asm("cvt.rn.bf16x2.f32 %0, %1, %2;" : "=r"(r) : "f"(hi), "f"(lo));
    return r;
}

__device__ __forceinline__ float2 bf2f(unsigned u) {
    __nv_bfloat162 h = *reinterpret_cast<__nv_bfloat162*>(&u);
    return make_float2(__low2float(h), __high2float(h));
}

__device__ __forceinline__ void mma_tf32(float* c,
                                         unsigned a0, unsigned a1, unsigned a2, unsigned a3,
                                         unsigned b0, unsigned b1) {
    asm volatile(
        "mma.sync.aligned.m16n8k8.row.col.f32.tf32.tf32.f32 "
        "{%0,%1,%2,%3},{%4,%5,%6,%7},{%8,%9},{%0,%1,%2,%3};"
        : "+f"(c[0]), "+f"(c[1]), "+f"(c[2]), "+f"(c[3])
        : "r"(a0), "r"(a1), "r"(a2), "r"(a3), "r"(b0), "r"(b1));
}

__device__ __forceinline__ void mma_bf16(float* c,
                                         unsigned a0, unsigned a1, unsigned a2, unsigned a3,
                                         unsigned b0, unsigned b1) {
    asm volatile(
        "mma.sync.aligned.m16n8k16.row.col.f32.bf16.bf16.f32 "
        "{%0,%1,%2,%3},{%4,%5,%6,%7},{%8,%9},{%0,%1,%2,%3};"
        : "+f"(c[0]), "+f"(c[1]), "+f"(c[2]), "+f"(c[3])
        : "r"(a0), "r"(a1), "r"(a2), "r"(a3), "r"(b0), "r"(b1));
}

// ---------------- zero scratch ----------------------------------------------
__global__ void k_zero() {
    int tid = blockIdx.x * blockDim.x + threadIdx.x;
    int stride = gridDim.x * blockDim.x;
    for (int i = tid; i < S2 * S2; i += stride) { g_G1[i] = 0.f; g_G2[i] = 0.f; }
    for (int i = tid; i < N; i += stride) {
        g_total[i] = 0.f; g_possim[i] = 0.f; g_posclq[i] = 0.f; g_posngh[i] = 0.f;
    }
    if (tid < 8) g_acc[tid] = 0.0;
}

// =================== fused layer A: factor (256 blocks) + proj (128) ========
#define PROJ_SMEM_FLOATS 21120

__device__ __forceinline__ void body_factor(const float* __restrict__ U0,
                                            const float* __restrict__ U1,
                                            const float* __restrict__ U2,
                                            float* dsm, int bx) {
    float* sU0 = dsm;            // [16][256]
    float* sU1 = dsm + 4096;     // [32][132]
    float* sW1 = dsm + 8320;     // [16][132]
    int t = threadIdx.x;
    int i0 = bx * 16;
#pragma unroll
    for (int q = 0; q < 16; q++) {
        int e = t + q * 256;
        int r = e >> 8, k = e & 255;
        sU0[r * 256 + k] = U0[(i0 + r) * S0 + k];
    }
    int ty = t >> 5, tx = t & 31;
    float accw[2][4];
#pragma unroll
    for (int i = 0; i < 2; i++)
#pragma unroll
        for (int k = 0; k < 4; k++) accw[i][k] = 0.f;
    for (int k0 = 0; k0 < S0; k0 += 32) {
        __syncthreads();
#pragma unroll
        for (int q = 0; q < 16; q++) {
            int e = t + q * 256;
            int kk = e >> 7, j = e & 127;
            sU1[kk * 132 + j] = U1[(k0 + kk) * S1 + j];
        }
        __syncthreads();
#pragma unroll
        for (int kk = 0; kk < 32; kk++) {
            float4 b = *reinterpret_cast<const float4*>(&sU1[kk * 132 + tx * 4]);
            float a0 = sU0[(ty * 2 + 0) * 256 + k0 + kk];
            float a1 = sU0[(ty * 2 + 1) * 256 + k0 + kk];
            accw[0][0] += a0 * b.x; accw[0][1] += a0 * b.y;
            accw[0][2] += a0 * b.z; accw[0][3] += a0 * b.w;
            accw[1][0] += a1 * b.x; accw[1][1] += a1 * b.y;
            accw[1][2] += a1 * b.z; accw[1][3] += a1 * b.w;
        }
    }
    __syncthreads();
#pragma unroll
    for (int i = 0; i < 2; i++)
        *reinterpret_cast<float4*>(&sW1[(ty * 2 + i) * 132 + tx * 4]) =
            make_float4(accw[i][0], accw[i][1], accw[i][2], accw[i][3]);
    __syncthreads();
    int tn = t >> 4, tc = t & 15;
    float acc2[4] = {0.f, 0.f, 0.f, 0.f};
#pragma unroll 4
    for (int k = 0; k < S1; k++) {
        float a = sW1[tn * 132 + k];
        float4 b = *reinterpret_cast<const float4*>(&U2[k * S2 + tc * 4]);
        acc2[0] += a * b.x; acc2[1] += a * b.y;
        acc2[2] += a * b.z; acc2[3] += a * b.w;
    }
    *reinterpret_cast<float4*>(&g_W2[(i0 + tn) * S2 + tc * 4]) =
        make_float4(acc2[0], acc2[1], acc2[2], acc2[3]);
}

__device__ __forceinline__ void body_proj(const float* __restrict__ V2,
                                          const float* __restrict__ fc1w,
                                          const float* __restrict__ fc1b,
                                          const float* __restrict__ fc2w,
                                          const float* __restrict__ fc2b,
                                          float* dsm, int bx) {
    float* sXT  = dsm;           // [64][40]
    float* sW1T = dsm + 2560;    // [64][132]
    float* sW2T = dsm;           // [128][132] (stage 2, aliases stage-1 arrays)
    float* sH1  = dsm + 16896;   // [32][132]
    int t = threadIdx.x;
    int n0 = bx * 32;
    int ty = t >> 5, tx = t & 31;

#pragma unroll
    for (int q = 0; q < 8; q++) {
        int e = t + q * 256;
        int s = e >> 5, n = e & 31;
        sXT[s * 40 + n] = V2[s * N + n0 + n];
    }
#pragma unroll
    for (int q = 0; q < 32; q++) {
        int e = t + q * 256;
        int j = e >> 6, s = e & 63;
        sW1T[s * 132 + j] = fc1w[e];
    }
    __syncthreads();

    float4 b1v = *reinterpret_cast<const float4*>(&fc1b[tx * 4]);
    float acc1[4][4];
#pragma unroll
    for (int i = 0; i < 4; i++) {
        acc1[i][0] = b1v.x; acc1[i][1] = b1v.y;
        acc1[i][2] = b1v.z; acc1[i][3] = b1v.w;
    }
#pragma unroll 4
    for (int s = 0; s < S2; s++) {
        float4 a = *reinterpret_cast<const float4*>(&sXT[s * 40 + ty * 4]);
        float4 b = *reinterpret_cast<const float4*>(&sW1T[s * 132 + tx * 4]);
        float av[4] = {a.x, a.y, a.z, a.w};
#pragma unroll
        for (int i = 0; i < 4; i++) {
            acc1[i][0] += av[i] * b.x; acc1[i][1] += av[i] * b.y;
            acc1[i][2] += av[i] * b.z; acc1[i][3] += av[i] * b.w;
        }
    }
#pragma unroll
    for (int i = 0; i < 4; i++) {
        float4 h;
        h.x = acc1[i][0] > 0.f ? acc1[i][0] : expm1f(acc1[i][0]);
        h.y = acc1[i][1] > 0.f ? acc1[i][1] : expm1f(acc1[i][1]);
        h.z = acc1[i][2] > 0.f ? acc1[i][2] : expm1f(acc1[i][2]);
        h.w = acc1[i][3] > 0.f ? acc1[i][3] : expm1f(acc1[i][3]);
        *reinterpret_cast<float4*>(&sH1[(ty * 4 + i) * 132 + tx * 4]) = h;
    }

    float h[2][4][4];
#pragma unroll
    for (int c = 0; c < 2; c++) {
        __syncthreads();
#pragma unroll
        for (int q = 0; q < 64; q++) {
            int e = t + q * 256;
            int lt = e >> 7, j = e & 127;
            sW2T[j * 132 + lt] = fc2w[(c * 128 + lt) * S1 + j];
        }
        __syncthreads();
        float4 b2v = *reinterpret_cast<const float4*>(&fc2b[c * 128 + tx * 4]);
#pragma unroll
        for (int i = 0; i < 4; i++) {
            h[c][i][0] = b2v.x; h[c][i][1] = b2v.y;
            h[c][i][2] = b2v.z; h[c][i][3] = b2v.w;
        }
#pragma unroll 4
        for (int j = 0; j < S1; j++) {
            float4 b = *reinterpret_cast<const float4*>(&sW2T[j * 132 + tx * 4]);
#pragma unroll
            for (int i = 0; i < 4; i++) {
                float a = sH1[(ty * 4 + i) * 132 + j];
                h[c][i][0] += a * b.x; h[c][i][1] += a * b.y;
                h[c][i][2] += a * b.z; h[c][i][3] += a * b.w;
            }
        }
    }
#pragma unroll
    for (int i = 0; i < 4; i++) {
        float ss = 0.f;
#pragma unroll
        for (int c = 0; c < 2; c++)
#pragma unroll
            for (int k = 0; k < 4; k++) ss += h[c][i][k] * h[c][i][k];
#pragma unroll
        for (int o = 16; o; o >>= 1) ss += __shfl_xor_sync(0xffffffffu, ss, o);
        float inv = 1.f / fmaxf(sqrtf(ss), 1e-12f);
        int row = n0 + ty * 4 + i;
#pragma unroll
        for (int c = 0; c < 2; c++) {
            unsigned p0 = bf16pack(h[c][i][0] * inv, h[c][i][1] * inv);
            unsigned p1 = bf16pack(h[c][i][2] * inv, h[c][i][3] * inv);
            *reinterpret_cast<uint2*>(&g_hnb[row * 128 + c * 64 + tx * 2]) =
                make_uint2(p0, p1);
        }
    }
}

__global__ __launch_bounds__(256) void k_fused_a(
    const float* __restrict__ U0, const float* __restrict__ U1,
    const float* __restrict__ U2, const float* __restrict__ V2,
    const float* __restrict__ fc1w, const float* __restrict__ fc1b,
    const float* __restrict__ fc2w, const float* __restrict__ fc2b) {
    extern __shared__ float dsm[];
    int b = blockIdx.x;
    if (b < 256) body_factor(U0, U1, U2, dsm, b);
    else         body_proj(V2, fc1w, fc1b, fc2w, fc2b, dsm, b - 256);
}

// =================== fused layer B bodies ===================================

// across: C = A @ V2^T tile held in registers; epilogue dots with g_W2
// directly (no partial buffers) + fused sumsq(A).
__device__ __forceinline__ void body_across(const float* __restrict__ A,
                                            const float* __restrict__ V2,
                                            unsigned* dsmu, int bx, int by) {
    unsigned* sA = dsmu;                 // [128][RPAD]
    unsigned* sV = dsmu + 128 * RPAD;    // [64][RPAD]
    int t = threadIdx.x;
    int lane = t & 31, warp = t >> 5;
    int wi = warp >> 1, ws = warp & 1;
    int g = lane >> 2, q4 = lane & 3;
    int i0 = bx * 128;
    int jbeg = by * (N / 8);
    int jend = jbeg + (N / 8);

    float acc[2][4][4];
#pragma unroll
    for (int m = 0; m < 2; m++)
#pragma unroll
        for (int n = 0; n < 4; n++)
#pragma unroll
            for (int q = 0; q < 4; q++) acc[m][n][q] = 0.f;
    float ssq = 0.f;

    int lrow = t >> 1, lhalf = t & 1;
    for (int j0 = jbeg; j0 < jend; j0 += 32) {
#pragma unroll
        for (int q = 0; q < 4; q++) {
            int c = lhalf * 16 + q * 4;
            float4 v = *reinterpret_cast<const float4*>(A + (i0 + lrow) * N + j0 + c);
            ssq += v.x * v.x + v.y * v.y + v.z * v.z + v.w * v.w;
            sA[lrow * RPAD + c + 0] = f2tf32(v.x);
            sA[lrow * RPAD + c + 1] = f2tf32(v.y);
            sA[lrow * RPAD + c + 2] = f2tf32(v.z);
            sA[lrow * RPAD + c + 3] = f2tf32(v.w);
        }
#pragma unroll
        for (int q = 0; q < 2; q++) {
            int e = t * 2 + q;
            int r = e >> 3, c = (e & 7) * 4;
            float4 v = *reinterpret_cast<const float4*>(V2 + r * N + j0 + c);
            sV[r * RPAD + c + 0] = f2tf32(v.x);
            sV[r * RPAD + c + 1] = f2tf32(v.y);
            sV[r * RPAD + c + 2] = f2tf32(v.z);
            sV[r * RPAD + c + 3] = f2tf32(v.w);
        }
        __syncthreads();
#pragma unroll
        for (int ks = 0; ks < 4; ks++) {
            int kk = ks * 8;
            unsigned a[2][4], b[4][2];
#pragma unroll
            for (int m = 0; m < 2; m++) {
                int r = wi * 32 + m * 16;
                a[m][0] = sA[(r + g) * RPAD + kk + q4];
                a[m][1] = sA[(r + g + 8) * RPAD + kk + q4];
                a[m][2] = sA[(r + g) * RPAD + kk + q4 + 4];
                a[m][3] = sA[(r + g + 8) * RPAD + kk + q4 + 4];
            }
#pragma unroll
            for (int n = 0; n < 4; n++) {
                int c = ws * 32 + n * 8;
                b[n][0] = sV[(c + g) * RPAD + kk + q4];
                b[n][1] = sV[(c + g) * RPAD + kk + q4 + 4];
            }
#pragma unroll
            for (int m = 0; m < 2; m++)
#pragma unroll
                for (int n = 0; n < 4; n++)
                    mma_tf32(acc[m][n], a[m][0], a[m][1], a[m][2], a[m][3],
                             b[n][0], b[n][1]);
        }
        __syncthreads();
    }
    float s1 = 0.f;
#pragma unroll
    for (int m = 0; m < 2; m++) {
        int r0 = i0 + wi * 32 + m * 16 + g;
#pragma unroll
        for (int n = 0; n < 4; n++) {
            int c = ws * 32 + n * 8 + q4 * 2;
            float2 w0 = *reinterpret_cast<const float2*>(g_W2 + r0 * S2 + c);
            float2 w1 = *reinterpret_cast<const float2*>(g_W2 + (r0 + 8) * S2 + c);
            s1 += acc[m][n][0] * w0.x + acc[m][n][1] * w0.y
                + acc[m][n][2] * w1.x + acc[m][n][3] * w1.y;
        }
    }
    float bs1 = blockReduceSum(s1);
    float bs0 = blockReduceSum(ssq);
    if (t == 0) {
        atomicAdd(&g_acc[1], (double)bs1);
        atomicAdd(&g_acc[0], (double)bs0);
    }
}

// refl: bf16 m16n8k16, symmetric upper-triangular tiles (528 blocks),
// software-pipelined global->smem staging.
__device__ __forceinline__ void body_refl(const float* __restrict__ sim,
                                          unsigned* dsmu, int b2) {
    // decode triangular index -> (by, bx), by <= bx
    int r = 0, base = 0;
    while (base + (32 - r) <= b2) { base += 32 - r; r++; }
    int by = r, bx = r + (b2 - base);
    bool offdiag = (bx != by);

    unsigned* sI = dsmu;                 // [128][HPAD] bf16x2 pairs
    unsigned* sJ = dsmu + 128 * HPAD;
    int t = threadIdx.x;
    int lane = t & 31, warp = t >> 5;
    int wi = warp >> 1, wj = warp & 1;
    int g = lane >> 2, q4 = lane & 3;
    int i0 = by * 128, j0 = bx * 128;

    float acc[2][8][4];
#pragma unroll
    for (int m = 0; m < 2; m++)
#pragma unroll
        for (int n = 0; n < 8; n++)
#pragma unroll
            for (int q = 0; q < 4; q++) acc[m][n][q] = 0.f;

    int lrow = t >> 1, lhalf = t & 1;
    const unsigned* srcI = g_hnb + (i0 + lrow) * 128 + lhalf * 8;
    const unsigned* srcJ = g_hnb + (j0 + lrow) * 128 + lhalf * 8;

    // prologue load (kp = 0)
    uint4 v0 = *reinterpret_cast<const uint4*>(srcI);
    uint4 v1 = *reinterpret_cast<const uint4*>(srcI + 4);
    uint4 w0 = *reinterpret_cast<const uint4*>(srcJ);
    uint4 w1 = *reinterpret_cast<const uint4*>(srcJ + 4);

#pragma unroll
    for (int kp = 0; kp < 128; kp += 16) {       // pair index; k step 32
        *reinterpret_cast<uint4*>(sI + lrow * HPAD + lhalf * 8)     = v0;
        *reinterpret_cast<uint4*>(sI + lrow * HPAD + lhalf * 8 + 4) = v1;
        *reinterpret_cast<uint4*>(sJ + lrow * HPAD + lhalf * 8)     = w0;
        *reinterpret_cast<uint4*>(sJ + lrow * HPAD + lhalf * 8 + 4) = w1;
        __syncthreads();
        if (kp + 16 < 128) {   // prefetch next tile; overlaps with mma below
            v0 = *reinterpret_cast<const uint4*>(srcI + kp + 16);
            v1 = *reinterpret_cast<const uint4*>(srcI + kp + 20);
            w0 = *reinterpret_cast<const uint4*>(srcJ + kp + 16);
            w1 = *reinterpret_cast<const uint4*>(srcJ + kp + 20);
        }
#pragma unroll
        for (int ks = 0; ks < 2; ks++) {         // two k16 mma steps
            int kk = ks * 8;                     // pair offset
            unsigned a[2][4], b[8][2];
#pragma unroll
            for (int m = 0; m < 2; m++) {
                int rr = wi * 32 + m * 16;
                a[m][0] = sI[(rr + g) * HPAD + kk + q4];
                a[m][1] = sI[(rr + g + 8) * HPAD + kk + q4];
                a[m][2] = sI[(rr + g) * HPAD + kk + q4 + 4];
                a[m][3] = sI[(rr + g + 8) * HPAD + kk + q4 + 4];
            }
#pragma unroll
            for (int n = 0; n < 8; n++) {
                int c = wj * 64 + n * 8;
                b[n][0] = sJ[(c + g) * HPAD + kk + q4];
                b[n][1] = sJ[(c + g) * HPAD + kk + q4 + 4];
            }
#pragma unroll
            for (int m = 0; m < 2; m++)
#pragma unroll
                for (int n = 0; n < 8; n++)
                    mma_bf16(acc[m][n], a[m][0], a[m][1], a[m][2], a[m][3],
                             b[n][0], b[n][1]);
        }
        __syncthreads();
    }

    // column accumulators (reuse smem arena; mainloop done after last sync)
    float* colT = reinterpret_cast<float*>(dsmu);        // [4][128]
    float* colP = reinterpret_cast<float*>(dsmu) + 512;  // [4][128]
    if (offdiag) {
        int cb = wj * 64;
        for (int x = lane; x < 64; x += 32) {
            colT[wi * 128 + cb + x] = 0.f;
            colP[wi * 128 + cb + x] = 0.f;
        }
        __syncwarp();
    }

#pragma unroll
    for (int m = 0; m < 2; m++) {
        float rs0 = 0.f, rs1 = 0.f, rp0 = 0.f, rp1 = 0.f;
        int r0 = i0 + wi * 32 + m * 16 + g;
#pragma unroll
        for (int n = 0; n < 8; n++) {
            int cl = wj * 64 + n * 8 + q4 * 2;
            int c = j0 + cl;
            float2 s0 = *reinterpret_cast<const float2*>(sim + r0 * N + c);
            float2 s1 = *reinterpret_cast<const float2*>(sim + (r0 + 8) * N + c);
            float e0 = __expf(2.f * acc[m][n][0]);
            float e1 = __expf(2.f * acc[m][n][1]);
            float e2 = __expf(2.f * acc[m][n][2]);
            float e3 = __expf(2.f * acc[m][n][3]);
            rs0 += e0 + e1;
            rs1 += e2 + e3;
            rp0 += (s0.x > 0.9f ? e0 : 0.f) + (s0.y > 0.9f ? e1 : 0.f);
            rp1 += (s1.x > 0.9f ? e2 : 0.f) + (s1.y > 0.9f ? e3 : 0.f);
            if (offdiag) {
                float ct0 = e0 + e2, ct1 = e1 + e3;
                float st00 = sim[c * N + r0],       st01 = sim[c * N + r0 + 8];
                float st10 = sim[(c + 1) * N + r0], st11 = sim[(c + 1) * N + r0 + 8];
                float cp0 = (st00 > 0.9f ? e0 : 0.f) + (st01 > 0.9f ? e2 : 0.f);
                float cp1 = (st10 > 0.9f ? e1 : 0.f) + (st11 > 0.9f ? e3 : 0.f);
#pragma unroll
                for (int o = 4; o <= 16; o <<= 1) {
                    ct0 += __shfl_xor_sync(0xffffffffu, ct0, o);
                    ct1 += __shfl_xor_sync(0xffffffffu, ct1, o);
                    cp0 += __shfl_xor_sync(0xffffffffu, cp0, o);
                    cp1 += __shfl_xor_sync(0xffffffffu, cp1, o);
                }
                if (lane < 4) {   // g == 0, lane == q4
                    colT[wi * 128 + cl]     += ct0;
                    colT[wi * 128 + cl + 1] += ct1;
                    colP[wi * 128 + cl]     += cp0;
                    colP[wi * 128 + cl + 1] += cp1;
                }
            }
        }
        rs0 += __shfl_xor_sync(0xffffffffu, rs0, 1);
        rs0 += __shfl_xor_sync(0xffffffffu, rs0, 2);
        rs1 += __shfl_xor_sync(0xffffffffu, rs1, 1);
        rs1 += __shfl_xor_sync(0xffffffffu, rs1, 2);
        rp0 += __shfl_xor_sync(0xffffffffu, rp0, 1);
        rp0 += __shfl_xor_sync(0xffffffffu, rp0, 2);
        rp1 += __shfl_xor_sync(0xffffffffu, rp1, 1);
        rp1 += __shfl_xor_sync(0xffffffffu, rp1, 2);
        if (q4 == 0) {
            atomicAdd(&g_total [r0],     rs0);
            atomicAdd(&g_possim[r0],     rp0);
            atomicAdd(&g_total [r0 + 8], rs1);
            atomicAdd(&g_possim[r0 + 8], rp1);
        }
    }

    if (offdiag) {
        __syncthreads();
        if (t < 128) {
            float ctot = colT[t] + colT[128 + t] + colT[256 + t] + colT[384 + t];
            float cpos = colP[t] + colP[128 + t] + colP[256 + t] + colP[384 + t];
            atomicAdd(&g_total [j0 + t], ctot);
            atomicAdd(&g_possim[j0 + t], cpos);
        }
    }
}

__device__ __forceinline__ void body_gram1(float* sT, int bx) {
    int t = threadIdx.x;
    int k0 = bx * 32;
#pragma unroll
    for (int q = 0; q < 8; q++) {
        int e = t + q * 256;
        int r = e >> 6, c = e & 63;
        sT[r * 68 + c] = g_W2[(k0 + r) * S2 + c];
    }
    __syncthreads();
    int a = (t >> 4) * 4, b = (t & 15) * 4;
    float acc[4][4];
#pragma unroll
    for (int i = 0; i < 4; i++)
#pragma unroll
        for (int k = 0; k < 4; k++) acc[i][k] = 0.f;
#pragma unroll 4
    for (int r = 0; r < 32; r++) {
        float4 va = *reinterpret_cast<const float4*>(&sT[r * 68 + a]);
        float4 vb = *reinterpret_cast<const float4*>(&sT[r * 68 + b]);
        float av[4] = {va.x, va.y, va.z, va.w};
#pragma unroll
        for (int i = 0; i < 4; i++) {
            acc[i][0] += av[i] * vb.x; acc[i][1] += av[i] * vb.y;
            acc[i][2] += av[i] * vb.z; acc[i][3] += av[i] * vb.w;
        }
    }
#pragma unroll
    for (int i = 0; i < 4; i++)
#pragma unroll
        for (int k = 0; k < 4; k++)
            atomicAdd(&g_G1[(a + i) * S2 + b + k], acc[i][k]);
}

__device__ __forceinline__ void body_gram2(const float* __restrict__ V2,
                                           float* sT, int bx) {
    int t = threadIdx.x;
    int j0 = bx * 32;
#pragma unroll
    for (int q = 0; q < 8; q++) {
        int e = t + q * 256;
        int s = e >> 5, j = e & 31;
        sT[j * 68 + s] = V2[s * N + j0 + j];
    }
    __syncthreads();
    int a = (t >> 4) * 4, b = (t & 15) * 4;
    float acc[4][4];
#pragma unroll
    for (int i = 0; i < 4; i++)
#pragma unroll
        for (int k = 0; k < 4; k++) acc[i][k] = 0.f;
#pragma unroll 4
    for (int j = 0; j < 32; j++) {
        float4 va = *reinterpret_cast<const float4*>(&sT[j * 68 + a]);
        float4 vb = *reinterpret_cast<const float4*>(&sT[j * 68 + b]);
        float av[4] = {va.x, va.y, va.z, va.w};
#pragma unroll
        for (int i = 0; i < 4; i++) {
            acc[i][0] += av[i] * vb.x; acc[i][1] += av[i] * vb.y;
            acc[i][2] += av[i] * vb.z; acc[i][3] += av[i] * vb.w;
        }
    }
#pragma unroll
    for (int i = 0; i < 4; i++)
#pragma unroll
        for (int k = 0; k < 4; k++)
            atomicAdd(&g_G2[(a + i) * S2 + b + k], acc[i][k]);
}

__device__ __forceinline__ void body_loss5(const float* __restrict__ U0,
                                           const float* __restrict__ U1,
                                           const float* __restrict__ U2,
                                           const float* __restrict__ V2, int bx) {
    int tid = bx * 256 + threadIdx.x;
    int stride = 128 * 256;
    float s = 0.f;
    for (int i = tid; i < N * S0; i += stride) { float v = U0[i]; if (v < 0.f) s += v * v; }
    for (int i = tid; i < S0 * S1; i += stride) { float v = U1[i]; if (v < 0.f) s += v * v; }
    for (int i = tid; i < S1 * S2; i += stride) { float v = U2[i]; if (v < 0.f) s += v * v; }
    for (int i = tid; i < S2 * N; i += stride) { float v = V2[i]; if (v < 0.f) s += v * v; }
    float bs = blockReduceSum(s);
    if (threadIdx.x == 0) atomicAdd(&g_acc[3], (double)bs);
}

__device__ __forceinline__ void body_gather(const int* __restrict__ clq,
                                            const int* __restrict__ ngh, int bx) {
    int tid = bx * 256 + threadIdx.x;
    if (tid >= N * 24) return;
    int i = tid / 24, m = tid % 24;
    int j; float* out;
    if (m < 8) {
        j = clq[i * 8 + m];
        for (int p = 0; p < m; p++) if (clq[i * 8 + p] == j) return;  // set semantics
        out = g_posclq;
    } else {
        int mm = m - 8;
        j = ngh[i * 16 + mm];
        for (int p = 0; p < mm; p++) if (ngh[i * 16 + p] == j) return;
        out = g_posngh;
    }
    const uint4* hi = reinterpret_cast<const uint4*>(g_hnb + i * 128);
    const uint4* hj = reinterpret_cast<const uint4*>(g_hnb + j * 128);
    float d = 0.f;
#pragma unroll 8
    for (int s = 0; s < 32; s++) {
        uint4 x = hi[s], y = hj[s];
        float2 a0 = bf2f(x.x), b0 = bf2f(y.x);
        float2 a1 = bf2f(x.y), b1 = bf2f(y.y);
        float2 a2 = bf2f(x.z), b2 = bf2f(y.z);
        float2 a3 = bf2f(x.w), b3 = bf2f(y.w);
        d += a0.x * b0.x + a0.y * b0.y + a1.x * b1.x + a1.y * b1.y
           + a2.x * b2.x + a2.y * b2.y + a3.x * b3.x + a3.y * b3.y;
    }
    atomicAdd(&out[i], expf(2.f * d));
}

// fused layer B: across[0,256) refl[256,784) gram1[784,912)
//                gram2[912,1040) loss5[1040,1168) gather[1168,1552)
__global__ __launch_bounds__(256) void k_fused_b(
    const float* __restrict__ A, const float* __restrict__ V2,
    const float* __restrict__ sim,
    const int* __restrict__ clq, const int* __restrict__ ngh,
    const float* __restrict__ U0, const float* __restrict__ U1,
    const float* __restrict__ U2) {
    extern __shared__ unsigned dsmu[];
    int b = blockIdx.x;
    if (b < 256) {
        body_across(A, V2, dsmu, b & 31, b >> 5);
    } else if (b < 784) {
        body_refl(sim, dsmu, b - 256);
    } else if (b < 912) {
        body_gram1(reinterpret_cast<float*>(dsmu), b - 784);
    } else if (b < 1040) {
        body_gram2(V2, reinterpret_cast<float*>(dsmu), b - 912);
    } else if (b < 1168) {
        body_loss5(U0, U1, U2, V2, b - 1040);
    } else {
        body_gather(clq, ngh, b - 1168);
    }
}

// =================== fused layer C: G1.G2 dot (8 blocks) + contrast (32) ====
__global__ __launch_bounds__(256) void k_fused_c() {
    int b = blockIdx.x;
    if (b < 8) {
        int tid = b * 256 + threadIdx.x;
        int stride = 8 * 256;
        float s2 = 0.f;
        for (int i = tid; i < S2 * S2; i += stride) s2 += g_G1[i] * g_G2[i];
        float b2 = blockReduceSum(s2);
        if (threadIdx.x == 0) atomicAdd(&g_acc[2], (double)b2);
    } else {
        int tid = (b - 8) * 256 + threadIdx.x;
        int stride = 32 * 256;
        float sc = 0.f, sn = 0.f, ssim = 0.f;
        for (int i = tid; i < N; i += stride) {
            float tot = g_total[i];
            float c1 = g_posclq[i] / tot;
            float c2 = g_posngh[i] / tot;
            float c3 = g_possim[i] / tot;
            if (c1 != 0.f) sc   -= __logf(c1);
            if (c2 != 0.f) sn   -= __logf(c2);
            if (c3 != 0.f) ssim -= __logf(c3);
        }
        float b1 = blockReduceSum(sc);
        float b2 = blockReduceSum(sn);
        float b3 = blockReduceSum(ssim);
        if (threadIdx.x == 0) {
            atomicAdd(&g_acc[4], (double)b1);
            atomicAdd(&g_acc[5], (double)b2);
            atomicAdd(&g_acc[6], (double)b3);
        }
    }
}

// ---------------- final combine ---------------------------------------------
__global__ void k_final(float* out) {
    double l1 = g_acc[0] - 2.0 * g_acc[1] + g_acc[2];
    double l2 = g_acc[4] / (double)N;
    double l3 = g_acc[5] / (double)N;
    double l4 = g_acc[6] / (double)N;
    double l5 = g_acc[3];
    double tot = l1 + 0.1 * l2 + 0.1 * l3 + 0.1 * l4 + l5;
    out[0] = (float)tot; out[1] = (float)l1; out[2] = (float)l2;
    out[3] = (float)l3;  out[4] = (float)l4; out[5] = (float)l5;
}

// ---------------- launch -----------------------------------------------------
extern "C" void kernel_launch(void* const* d_in, const int* in_sizes, int n_in,
                              void* d_out, int out_size) {
    const float* A    = (const float*)d_in[0];
    const float* U0   = (const float*)d_in[1];
    const float* U1   = (const float*)d_in[2];
    const float* U2   = (const float*)d_in[3];
    const float* V2   = (const float*)d_in[4];
    const float* fc1w = (const float*)d_in[5];
    const float* fc1b = (const float*)d_in[6];
    const float* fc2w = (const float*)d_in[7];
    const float* fc2b = (const float*)d_in[8];
    const float* sim  = (const float*)d_in[9];
    const int*   clq  = (const int*)d_in[10];
    const int*   ngh  = (const int*)d_in[11];
    float* out = (float*)d_out;

    static bool attr_done = false;
    if (!attr_done) {
        cudaFuncSetAttribute(k_fused_a, cudaFuncAttributeMaxDynamicSharedMemorySize,
                             PROJ_SMEM_FLOATS * 4);
        attr_done = true;
    }

    k_zero<<<64, 256>>>();
    k_fused_a<<<384, 256, PROJ_SMEM_FLOATS * 4>>>(U0, U1, U2, V2,
                                                  fc1w, fc1b, fc2w, fc2b);
    k_fused_b<<<1552, 256, (128 + 64) * RPAD * 4>>>(A, V2, sim, clq, ngh, U0, U1, U2);
    k_fused_c<<<40, 256>>>();
    k_final<<<1, 1>>>(out);
}